// round 1
// baseline (speedup 1.0000x reference)
#include <cuda_runtime.h>
#include <cuda_bf16.h>
#include <math.h>

#define N_NODES 50000
#define N_EDGES 1600000
#define F_IN    256
#define F1T     200   // H1*F1
#define NH1     2
#define C_OUT   32
#define NEG_SLOPE 0.2f

// ---------------- scratch (static device globals; no allocation) ----------------
__device__ int   g_cnt[N_NODES];
__device__ int   g_off[N_NODES + 1];
__device__ int   g_cur[N_NODES];
__device__ int   g_psrc[N_EDGES];            // src node of each edge, grouped by dst
__device__ float g_z1[(size_t)N_NODES * F1T];   // 40 MB
__device__ float g_el1[N_NODES * NH1];
__device__ float g_er1[N_NODES * NH1];
__device__ float g_h1[(size_t)N_NODES * F1T];   // 40 MB
__device__ float g_z2[(size_t)N_NODES * C_OUT]; // 6.4 MB
__device__ float g_el2[N_NODES];
__device__ float g_er2[N_NODES];

// ---------------- helpers ----------------
__device__ __forceinline__ float warp_sum(float v) {
    #pragma unroll
    for (int o = 16; o; o >>= 1) v += __shfl_xor_sync(0xffffffffu, v, o);
    return v;
}
__device__ __forceinline__ float warp_max(float v) {
    #pragma unroll
    for (int o = 16; o; o >>= 1) v = fmaxf(v, __shfl_xor_sync(0xffffffffu, v, o));
    return v;
}
__device__ __forceinline__ float lrelu(float x) { return x > 0.f ? x : NEG_SLOPE * x; }
__device__ __forceinline__ float elu1(float x)  { return x > 0.f ? x : (__expf(x) - 1.f); }

// ---------------- CSR build ----------------
__global__ void k_zero_cnt() {
    int i = blockIdx.x * blockDim.x + threadIdx.x;
    if (i < N_NODES) g_cnt[i] = 0;
}

__global__ void k_hist(const int* __restrict__ dst) {
    int e = blockIdx.x * blockDim.x + threadIdx.x;
    if (e < N_EDGES) atomicAdd(&g_cnt[dst[e]], 1);
}

__global__ void k_scan() {   // single block, 1024 threads
    const int T = 1024;
    const int CH = (N_NODES + T - 1) / T;  // 49
    int tid = threadIdx.x;
    int beg = tid * CH;
    int end = min(beg + CH, N_NODES);
    int s = 0;
    for (int i = beg; i < end; i++) s += g_cnt[i];

    __shared__ int warp_sums[32];
    int lane = tid & 31, wid = tid >> 5;
    int v = s;
    #pragma unroll
    for (int o = 1; o < 32; o <<= 1) {
        int t = __shfl_up_sync(0xffffffffu, v, o);
        if (lane >= o) v += t;
    }
    if (lane == 31) warp_sums[wid] = v;
    __syncthreads();
    if (wid == 0) {
        int w = warp_sums[lane];
        #pragma unroll
        for (int o = 1; o < 32; o <<= 1) {
            int t = __shfl_up_sync(0xffffffffu, w, o);
            if (lane >= o) w += t;
        }
        warp_sums[lane] = w;
    }
    __syncthreads();
    int excl = (v - s) + (wid > 0 ? warp_sums[wid - 1] : 0);
    int run = excl;
    for (int i = beg; i < end; i++) {
        int c = g_cnt[i];
        g_off[i] = run;
        g_cur[i] = run;
        run += c;
    }
    if (tid == T - 1) g_off[N_NODES] = run;
}

__global__ void k_scatter(const int* __restrict__ src, const int* __restrict__ dst) {
    int e = blockIdx.x * blockDim.x + threadIdx.x;
    if (e < N_EDGES) {
        int p = atomicAdd(&g_cur[dst[e]], 1);
        g_psrc[p] = src[e];
    }
}

// ---------------- GEMM1: z1 = features @ W1   [50000,256] x [256,200] ----------------
#define BM 64
#define BN 64
#define BK 16
__global__ __launch_bounds__(256) void k_gemm1(const float* __restrict__ A,
                                               const float* __restrict__ B) {
    __shared__ float sA[BK][BM + 4];   // padded: transposed A tile
    __shared__ float sB[BK][BN];
    int tid = threadIdx.x;
    int bm = blockIdx.x * BM;
    int bn = blockIdx.y * BN;
    int tx = tid & 15, ty = tid >> 4;

    int am = tid >> 2, ak = (tid & 3) * 4;   // A tile loader coords
    int bk = tid >> 4, bcol = (tid & 15) * 4; // B tile loader coords

    float acc[4][4] = {};

    for (int k0 = 0; k0 < F_IN; k0 += BK) {
        float4 a4 = make_float4(0.f, 0.f, 0.f, 0.f);
        if (bm + am < N_NODES)
            a4 = *(const float4*)&A[(size_t)(bm + am) * F_IN + k0 + ak];
        sA[ak + 0][am] = a4.x; sA[ak + 1][am] = a4.y;
        sA[ak + 2][am] = a4.z; sA[ak + 3][am] = a4.w;

        float4 b4 = make_float4(0.f, 0.f, 0.f, 0.f);
        if (bn + bcol < F1T)
            b4 = *(const float4*)&B[(size_t)(k0 + bk) * F1T + bn + bcol];
        *(float4*)&sB[bk][bcol] = b4;
        __syncthreads();

        #pragma unroll
        for (int k = 0; k < BK; k++) {
            float4 av = *(const float4*)&sA[k][ty * 4];
            float4 bv = *(const float4*)&sB[k][tx * 4];
            float ar_[4] = {av.x, av.y, av.z, av.w};
            float br_[4] = {bv.x, bv.y, bv.z, bv.w};
            #pragma unroll
            for (int i = 0; i < 4; i++)
                #pragma unroll
                for (int j = 0; j < 4; j++)
                    acc[i][j] += ar_[i] * br_[j];
        }
        __syncthreads();
    }

    #pragma unroll
    for (int i = 0; i < 4; i++) {
        int r = bm + ty * 4 + i;
        if (r >= N_NODES) continue;
        #pragma unroll
        for (int j = 0; j < 4; j++) {
            int c = bn + tx * 4 + j;
            if (c < F1T) g_z1[(size_t)r * F1T + c] = acc[i][j];
        }
    }
}

// ---------------- attention coefficients, layer 1 ----------------
__global__ __launch_bounds__(256) void k_attn1(const float* __restrict__ al,
                                               const float* __restrict__ ar) {
    int w = (blockIdx.x * blockDim.x + threadIdx.x) >> 5;
    if (w >= N_NODES) return;
    int lane = threadIdx.x & 31;
    const float* z = g_z1 + (size_t)w * F1T;
    float e0l = 0.f, e0r = 0.f, e1l = 0.f, e1r = 0.f;
    for (int f = lane; f < F1T; f += 32) {
        float v = z[f];
        float a = al[f], r = ar[f];   // flat [H1*F1] matches flat z layout
        if (f < 100) { e0l += v * a; e0r += v * r; }
        else         { e1l += v * a; e1r += v * r; }
    }
    e0l = warp_sum(e0l); e0r = warp_sum(e0r);
    e1l = warp_sum(e1l); e1r = warp_sum(e1r);
    if (lane == 0) {
        g_el1[2 * w] = e0l; g_el1[2 * w + 1] = e1l;
        g_er1[2 * w] = e0r; g_er1[2 * w + 1] = e1r;
    }
}

// ---------------- layer-1 aggregation: edge softmax + weighted sum + bias + ELU ----------------
__global__ __launch_bounds__(256) void k_agg1(const float* __restrict__ b1) {
    int w = (blockIdx.x * 256 + threadIdx.x) >> 5;
    if (w >= N_NODES) return;
    int lane = threadIdx.x & 31;
    int beg = g_off[w], end = g_off[w + 1];
    float er0 = g_er1[2 * w], er1v = g_er1[2 * w + 1];

    float m0 = -3.402823466e38f, m1 = -3.402823466e38f;
    for (int i = beg + lane; i < end; i += 32) {
        int s = g_psrc[i];
        float2 el = *(const float2*)&g_el1[2 * s];
        m0 = fmaxf(m0, lrelu(el.x + er0));
        m1 = fmaxf(m1, lrelu(el.y + er1v));
    }
    m0 = warp_max(m0); m1 = warp_max(m1);

    float d0 = 0.f, d1 = 0.f;
    for (int i = beg + lane; i < end; i += 32) {
        int s = g_psrc[i];
        float2 el = *(const float2*)&g_el1[2 * s];
        d0 += __expf(lrelu(el.x + er0) - m0);
        d1 += __expf(lrelu(el.y + er1v) - m1);
    }
    d0 = warp_sum(d0); d1 = warp_sum(d1);
    float inv0 = d0 > 0.f ? 1.f / d0 : 0.f;
    float inv1 = d1 > 0.f ? 1.f / d1 : 0.f;

    // lane covers features f=4*lane (0..127) and f=128+4*lane (lane<18 -> 128..199)
    float4 acc0 = make_float4(0.f, 0.f, 0.f, 0.f);
    float4 acc1 = make_float4(0.f, 0.f, 0.f, 0.f);
    bool has2 = lane < 18;
    for (int i = beg; i < end; i++) {
        int s = g_psrc[i];
        float2 el = *(const float2*)&g_el1[2 * s];
        float a0 = __expf(lrelu(el.x + er0) - m0) * inv0;
        float a1 = __expf(lrelu(el.y + er1v) - m1) * inv1;
        const float* zr = g_z1 + (size_t)s * F1T;
        float4 v = *(const float4*)&zr[4 * lane];
        float aa = (lane < 25) ? a0 : a1;   // head boundary at f=100 aligns to 4
        acc0.x += v.x * aa; acc0.y += v.y * aa;
        acc0.z += v.z * aa; acc0.w += v.w * aa;
        if (has2) {
            float4 v2 = *(const float4*)&zr[128 + 4 * lane];
            acc1.x += v2.x * a1; acc1.y += v2.y * a1;
            acc1.z += v2.z * a1; acc1.w += v2.w * a1;
        }
    }

    float* out = g_h1 + (size_t)w * F1T;
    float4 bb = *(const float4*)&b1[4 * lane];
    float4 o;
    o.x = elu1(acc0.x + bb.x); o.y = elu1(acc0.y + bb.y);
    o.z = elu1(acc0.z + bb.z); o.w = elu1(acc0.w + bb.w);
    *(float4*)&out[4 * lane] = o;
    if (has2) {
        float4 bb2 = *(const float4*)&b1[128 + 4 * lane];
        float4 o2;
        o2.x = elu1(acc1.x + bb2.x); o2.y = elu1(acc1.y + bb2.y);
        o2.z = elu1(acc1.z + bb2.z); o2.w = elu1(acc1.w + bb2.w);
        *(float4*)&out[128 + 4 * lane] = o2;
    }
}

// ---------------- GEMM2 + attn coefs layer 2: z2 = h1 @ W2, el2/er2 ----------------
__global__ __launch_bounds__(256) void k_gemm2(const float* __restrict__ W2,
                                               const float* __restrict__ al2,
                                               const float* __restrict__ ar2) {
    __shared__ float sW[F1T * C_OUT];   // 25.6 KB
    __shared__ float sal[C_OUT], sar[C_OUT];
    int tid = threadIdx.x;
    for (int i = tid; i < F1T * C_OUT; i += 256) sW[i] = W2[i];
    if (tid < C_OUT) { sal[tid] = al2[tid]; sar[tid] = ar2[tid]; }
    __syncthreads();

    int lane = tid & 31;
    int w = blockIdx.x * 8 + (tid >> 5);
    if (w >= N_NODES) return;
    const float* h = g_h1 + (size_t)w * F1T;
    float acc = 0.f;
    #pragma unroll 5
    for (int k = 0; k < F1T; k += 4) {
        float4 x = *(const float4*)&h[k];
        acc += x.x * sW[(k + 0) * C_OUT + lane];
        acc += x.y * sW[(k + 1) * C_OUT + lane];
        acc += x.z * sW[(k + 2) * C_OUT + lane];
        acc += x.w * sW[(k + 3) * C_OUT + lane];
    }
    g_z2[(size_t)w * C_OUT + lane] = acc;
    float el = warp_sum(acc * sal[lane]);
    float er = warp_sum(acc * sar[lane]);
    if (lane == 0) { g_el2[w] = el; g_er2[w] = er; }
}

// ---------------- layer-2 aggregation -> output ----------------
__global__ __launch_bounds__(256) void k_agg2(const float* __restrict__ b2,
                                              float* __restrict__ out) {
    int w = (blockIdx.x * 256 + threadIdx.x) >> 5;
    if (w >= N_NODES) return;
    int lane = threadIdx.x & 31;
    int beg = g_off[w], end = g_off[w + 1];
    float ern = g_er2[w];

    float m = -3.402823466e38f;
    for (int i = beg + lane; i < end; i += 32)
        m = fmaxf(m, lrelu(g_el2[g_psrc[i]] + ern));
    m = warp_max(m);

    float d = 0.f;
    for (int i = beg + lane; i < end; i += 32)
        d += __expf(lrelu(g_el2[g_psrc[i]] + ern) - m);
    d = warp_sum(d);
    float inv = d > 0.f ? 1.f / d : 0.f;

    float acc = 0.f;
    for (int i = beg; i < end; i++) {
        int s = g_psrc[i];
        float a = __expf(lrelu(g_el2[s] + ern) - m) * inv;
        acc += g_z2[(size_t)s * C_OUT + lane] * a;
    }
    out[(size_t)w * C_OUT + lane] = acc + b2[lane];
}

// ---------------- launch ----------------
extern "C" void kernel_launch(void* const* d_in, const int* in_sizes, int n_in,
                              void* d_out, int out_size) {
    const float* features = (const float*)d_in[0];
    const float* W1  = (const float*)d_in[1];
    const float* al1 = (const float*)d_in[2];
    const float* ar1 = (const float*)d_in[3];
    const float* b1  = (const float*)d_in[4];
    const float* W2  = (const float*)d_in[5];
    const float* al2 = (const float*)d_in[6];
    const float* ar2 = (const float*)d_in[7];
    const float* b2  = (const float*)d_in[8];
    const int*   src = (const int*)d_in[9];
    const int*   dst = (const int*)d_in[10];
    float* out = (float*)d_out;

    // CSR build (grouped by dst)
    k_zero_cnt<<<(N_NODES + 255) / 256, 256>>>();
    k_hist<<<N_EDGES / 256, 256>>>(dst);
    k_scan<<<1, 1024>>>();
    k_scatter<<<N_EDGES / 256, 256>>>(src, dst);

    // layer 1
    dim3 g1((N_NODES + BM - 1) / BM, (F1T + BN - 1) / BN);
    k_gemm1<<<g1, 256>>>(features, W1);
    k_attn1<<<(N_NODES * 32 + 255) / 256, 256>>>(al1, ar1);
    k_agg1<<<N_NODES / 8, 256>>>(b1);

    // layer 2
    k_gemm2<<<N_NODES / 8, 256>>>(W2, al2, ar2);
    k_agg2<<<N_NODES / 8, 256>>>(b2, out);
}

// round 2
// speedup vs baseline: 1.1388x; 1.1388x over previous
#include <cuda_runtime.h>
#include <cuda_bf16.h>
#include <math.h>

#define N_NODES 50000
#define N_EDGES 1600000
#define F_IN    256
#define F1T     200   // H1*F1
#define NH1     2
#define C_OUT   32
#define NEG_SLOPE 0.2f

// ---------------- scratch (static device globals; no allocation) ----------------
__device__ int   g_cnt[N_NODES];
__device__ int   g_off[N_NODES + 1];
__device__ int   g_cur[N_NODES];
__device__ int   g_psrc[N_EDGES];            // src node of each edge, grouped by dst
__device__ float g_z1[(size_t)N_NODES * F1T];   // 40 MB
__device__ float g_el1[N_NODES * NH1];
__device__ float g_er1[N_NODES * NH1];
__device__ float g_h1[(size_t)N_NODES * F1T];   // 40 MB
__device__ float g_z2[(size_t)N_NODES * C_OUT]; // 6.4 MB
__device__ float g_el2[N_NODES];
__device__ float g_er2[N_NODES];

// ---------------- helpers ----------------
__device__ __forceinline__ float warp_sum(float v) {
    #pragma unroll
    for (int o = 16; o; o >>= 1) v += __shfl_xor_sync(0xffffffffu, v, o);
    return v;
}
__device__ __forceinline__ float lrelu(float x) { return x > 0.f ? x : NEG_SLOPE * x; }
__device__ __forceinline__ float elu1(float x)  { return x > 0.f ? x : (__expf(x) - 1.f); }
__device__ __forceinline__ float tf32r(float x) {
    unsigned u;
    asm("cvt.rna.tf32.f32 %0, %1;" : "=r"(u) : "f"(x));
    return __uint_as_float(u);
}

// ---------------- CSR build ----------------
__global__ void k_zero_cnt() {
    int i = blockIdx.x * blockDim.x + threadIdx.x;
    if (i < N_NODES) g_cnt[i] = 0;
}

__global__ void k_hist(const int* __restrict__ dst) {
    int e = blockIdx.x * blockDim.x + threadIdx.x;
    if (e < N_EDGES) atomicAdd(&g_cnt[dst[e]], 1);
}

__global__ void k_scan() {   // single block, 1024 threads
    const int T = 1024;
    const int CH = (N_NODES + T - 1) / T;  // 49
    int tid = threadIdx.x;
    int beg = tid * CH;
    int end = min(beg + CH, N_NODES);
    int s = 0;
    for (int i = beg; i < end; i++) s += g_cnt[i];

    __shared__ int warp_sums[32];
    int lane = tid & 31, wid = tid >> 5;
    int v = s;
    #pragma unroll
    for (int o = 1; o < 32; o <<= 1) {
        int t = __shfl_up_sync(0xffffffffu, v, o);
        if (lane >= o) v += t;
    }
    if (lane == 31) warp_sums[wid] = v;
    __syncthreads();
    if (wid == 0) {
        int w = warp_sums[lane];
        #pragma unroll
        for (int o = 1; o < 32; o <<= 1) {
            int t = __shfl_up_sync(0xffffffffu, w, o);
            if (lane >= o) w += t;
        }
        warp_sums[lane] = w;
    }
    __syncthreads();
    int excl = (v - s) + (wid > 0 ? warp_sums[wid - 1] : 0);
    int run = excl;
    for (int i = beg; i < end; i++) {
        int c = g_cnt[i];
        g_off[i] = run;
        g_cur[i] = run;
        run += c;
    }
    if (tid == T - 1) g_off[N_NODES] = run;
}

__global__ void k_scatter(const int* __restrict__ src, const int* __restrict__ dst) {
    int e = blockIdx.x * blockDim.x + threadIdx.x;
    if (e < N_EDGES) {
        int p = atomicAdd(&g_cur[dst[e]], 1);
        g_psrc[p] = src[e];
    }
}

// ---------------- GEMM1 (tf32 tensor core): z1 = features @ W1 ----------------
// [50000,256] x [256,200] via mma.sync.m16n8k8.tf32
#define G1_BM 128
#define G1_BN 64
#define G1_BK 32
#define G1_LDA (G1_BM + 8)   // stride 136 -> conflict-free frag loads
#define G1_LDB (G1_BN + 8)   // stride 72

__device__ __forceinline__ void mma_tf32(float* d, const unsigned* a, const unsigned* b) {
    asm volatile(
        "mma.sync.aligned.m16n8k8.row.col.f32.tf32.tf32.f32 "
        "{%0,%1,%2,%3}, {%4,%5,%6,%7}, {%8,%9}, {%0,%1,%2,%3};"
        : "+f"(d[0]), "+f"(d[1]), "+f"(d[2]), "+f"(d[3])
        : "r"(a[0]), "r"(a[1]), "r"(a[2]), "r"(a[3]), "r"(b[0]), "r"(b[1]));
}

__global__ __launch_bounds__(256) void k_gemm1_tc(const float* __restrict__ A,
                                                  const float* __restrict__ B) {
    __shared__ float sA[G1_BK][G1_LDA];
    __shared__ float sB[G1_BK][G1_LDB];
    int tid = threadIdx.x;
    int lane = tid & 31, wid = tid >> 5;
    int wm = wid & 3, wn = wid >> 2;          // 4 x 2 warp grid
    int bm = blockIdx.x * G1_BM, bn = blockIdx.y * G1_BN;

    float acc[2][4][4] = {};                  // [mTile16][nTile8][frag]

    int q = lane >> 2, r = lane & 3;          // fragment coords

    for (int k0 = 0; k0 < F_IN; k0 += G1_BK) {
        // load A tile (128 x 32), transpose into sA[k][m], round to tf32
        #pragma unroll
        for (int it = 0; it < 4; it++) {
            int idx = tid + it * 256;         // 0..1023
            int m = idx >> 3;                 // 0..127
            int kk = (idx & 7) << 2;          // 0..28
            float4 v = make_float4(0.f, 0.f, 0.f, 0.f);
            if (bm + m < N_NODES)
                v = *(const float4*)&A[(size_t)(bm + m) * F_IN + k0 + kk];
            sA[kk + 0][m] = tf32r(v.x);
            sA[kk + 1][m] = tf32r(v.y);
            sA[kk + 2][m] = tf32r(v.z);
            sA[kk + 3][m] = tf32r(v.w);
        }
        // load B tile (32 x 64) into sB[k][n], round to tf32
        #pragma unroll
        for (int it = 0; it < 2; it++) {
            int idx = tid + it * 256;         // 0..511
            int kk = idx >> 4;                // 0..31
            int n = (idx & 15) << 2;          // 0..60
            float4 v = make_float4(0.f, 0.f, 0.f, 0.f);
            if (bn + n < F1T)
                v = *(const float4*)&B[(size_t)(k0 + kk) * F1T + bn + n];
            sB[kk][n + 0] = tf32r(v.x);
            sB[kk][n + 1] = tf32r(v.y);
            sB[kk][n + 2] = tf32r(v.z);
            sB[kk][n + 3] = tf32r(v.w);
        }
        __syncthreads();

        #pragma unroll
        for (int k8 = 0; k8 < G1_BK / 8; k8++) {
            int kb = k8 * 8;
            unsigned af[2][4], bf[4][2];
            #pragma unroll
            for (int mt = 0; mt < 2; mt++) {
                int m0 = wm * 32 + mt * 16 + q;
                af[mt][0] = __float_as_uint(sA[kb + r][m0]);
                af[mt][1] = __float_as_uint(sA[kb + r][m0 + 8]);
                af[mt][2] = __float_as_uint(sA[kb + r + 4][m0]);
                af[mt][3] = __float_as_uint(sA[kb + r + 4][m0 + 8]);
            }
            #pragma unroll
            for (int nt = 0; nt < 4; nt++) {
                int n0 = wn * 32 + nt * 8 + q;
                bf[nt][0] = __float_as_uint(sB[kb + r][n0]);
                bf[nt][1] = __float_as_uint(sB[kb + r + 4][n0]);
            }
            #pragma unroll
            for (int mt = 0; mt < 2; mt++)
                #pragma unroll
                for (int nt = 0; nt < 4; nt++)
                    mma_tf32(acc[mt][nt], af[mt], bf[nt]);
        }
        __syncthreads();
    }

    // store C: thread holds (row q, col 2r)/(row q+8) per 16x8 tile
    #pragma unroll
    for (int mt = 0; mt < 2; mt++) {
        #pragma unroll
        for (int nt = 0; nt < 4; nt++) {
            int row = bm + wm * 32 + mt * 16 + q;
            int col = bn + wn * 32 + nt * 8 + 2 * r;
            if (col < F1T) {
                if (row < N_NODES) {
                    float* p = &g_z1[(size_t)row * F1T + col];
                    p[0] = acc[mt][nt][0];
                    p[1] = acc[mt][nt][1];
                }
                if (row + 8 < N_NODES) {
                    float* p = &g_z1[(size_t)(row + 8) * F1T + col];
                    p[0] = acc[mt][nt][2];
                    p[1] = acc[mt][nt][3];
                }
            }
        }
    }
}

// ---------------- attention coefficients, layer 1 ----------------
__global__ __launch_bounds__(256) void k_attn1(const float* __restrict__ al,
                                               const float* __restrict__ ar) {
    int w = (blockIdx.x * blockDim.x + threadIdx.x) >> 5;
    if (w >= N_NODES) return;
    int lane = threadIdx.x & 31;
    const float* z = g_z1 + (size_t)w * F1T;
    float e0l = 0.f, e0r = 0.f, e1l = 0.f, e1r = 0.f;
    for (int f = lane; f < F1T; f += 32) {
        float v = z[f];
        float a = al[f], rr = ar[f];
        if (f < 100) { e0l += v * a; e0r += v * rr; }
        else         { e1l += v * a; e1r += v * rr; }
    }
    e0l = warp_sum(e0l); e0r = warp_sum(e0r);
    e1l = warp_sum(e1l); e1r = warp_sum(e1r);
    if (lane == 0) {
        g_el1[2 * w] = e0l; g_el1[2 * w + 1] = e1l;
        g_er1[2 * w] = e0r; g_er1[2 * w + 1] = e1r;
    }
}

// ---------------- layer-1 aggregation (no max pass; exp(e)/sum exp(e)) ----------------
__global__ __launch_bounds__(256) void k_agg1(const float* __restrict__ b1) {
    int w = (blockIdx.x * 256 + threadIdx.x) >> 5;
    if (w >= N_NODES) return;
    int lane = threadIdx.x & 31;
    int beg = g_off[w], end = g_off[w + 1];
    float er0 = g_er1[2 * w], er1v = g_er1[2 * w + 1];

    // denominators
    float d0 = 0.f, d1 = 0.f;
    for (int i = beg + lane; i < end; i += 32) {
        int s = g_psrc[i];
        float2 el = *(const float2*)&g_el1[2 * s];
        d0 += __expf(lrelu(el.x + er0));
        d1 += __expf(lrelu(el.y + er1v));
    }
    d0 = warp_sum(d0); d1 = warp_sum(d1);
    float inv0 = d0 > 0.f ? 1.f / d0 : 0.f;
    float inv1 = d1 > 0.f ? 1.f / d1 : 0.f;

    // weighted sum: lane covers f=4*lane and f=128+4*lane (lane<18)
    float4 acc0 = make_float4(0.f, 0.f, 0.f, 0.f);
    float4 acc1 = make_float4(0.f, 0.f, 0.f, 0.f);
    bool has2 = lane < 18;
    float selA = (lane < 25) ? 1.f : 0.f;   // head boundary at f=100

    int i = beg;
    for (; i + 1 < end; i += 2) {
        int s0 = g_psrc[i], s1 = g_psrc[i + 1];
        float2 ea = *(const float2*)&g_el1[2 * s0];
        float2 eb = *(const float2*)&g_el1[2 * s1];
        const float* zr0 = g_z1 + (size_t)s0 * F1T;
        const float* zr1 = g_z1 + (size_t)s1 * F1T;
        float4 va = *(const float4*)&zr0[4 * lane];
        float4 vb = *(const float4*)&zr1[4 * lane];
        float a0a = __expf(lrelu(ea.x + er0)) * inv0;
        float a1a = __expf(lrelu(ea.y + er1v)) * inv1;
        float a0b = __expf(lrelu(eb.x + er0)) * inv0;
        float a1b = __expf(lrelu(eb.y + er1v)) * inv1;
        float wa = selA * a0a + (1.f - selA) * a1a;
        float wb = selA * a0b + (1.f - selA) * a1b;
        acc0.x += va.x * wa + vb.x * wb;
        acc0.y += va.y * wa + vb.y * wb;
        acc0.z += va.z * wa + vb.z * wb;
        acc0.w += va.w * wa + vb.w * wb;
        if (has2) {
            float4 v2a = *(const float4*)&zr0[128 + 4 * lane];
            float4 v2b = *(const float4*)&zr1[128 + 4 * lane];
            acc1.x += v2a.x * a1a + v2b.x * a1b;
            acc1.y += v2a.y * a1a + v2b.y * a1b;
            acc1.z += v2a.z * a1a + v2b.z * a1b;
            acc1.w += v2a.w * a1a + v2b.w * a1b;
        }
    }
    if (i < end) {
        int s = g_psrc[i];
        float2 el = *(const float2*)&g_el1[2 * s];
        float a0 = __expf(lrelu(el.x + er0)) * inv0;
        float a1 = __expf(lrelu(el.y + er1v)) * inv1;
        const float* zr = g_z1 + (size_t)s * F1T;
        float4 v = *(const float4*)&zr[4 * lane];
        float aa = selA * a0 + (1.f - selA) * a1;
        acc0.x += v.x * aa; acc0.y += v.y * aa;
        acc0.z += v.z * aa; acc0.w += v.w * aa;
        if (has2) {
            float4 v2 = *(const float4*)&zr[128 + 4 * lane];
            acc1.x += v2.x * a1; acc1.y += v2.y * a1;
            acc1.z += v2.z * a1; acc1.w += v2.w * a1;
        }
    }

    float* out = g_h1 + (size_t)w * F1T;
    float4 bb = *(const float4*)&b1[4 * lane];
    float4 o;
    o.x = elu1(acc0.x + bb.x); o.y = elu1(acc0.y + bb.y);
    o.z = elu1(acc0.z + bb.z); o.w = elu1(acc0.w + bb.w);
    *(float4*)&out[4 * lane] = o;
    if (has2) {
        float4 bb2 = *(const float4*)&b1[128 + 4 * lane];
        float4 o2;
        o2.x = elu1(acc1.x + bb2.x); o2.y = elu1(acc1.y + bb2.y);
        o2.z = elu1(acc1.z + bb2.z); o2.w = elu1(acc1.w + bb2.w);
        *(float4*)&out[128 + 4 * lane] = o2;
    }
}

// ---------------- GEMM2 + attn coefs layer 2 ----------------
__global__ __launch_bounds__(256) void k_gemm2(const float* __restrict__ W2,
                                               const float* __restrict__ al2,
                                               const float* __restrict__ ar2) {
    __shared__ float sW[F1T * C_OUT];   // 25.6 KB
    __shared__ float sal[C_OUT], sar[C_OUT];
    int tid = threadIdx.x;
    for (int i = tid; i < F1T * C_OUT; i += 256) sW[i] = W2[i];
    if (tid < C_OUT) { sal[tid] = al2[tid]; sar[tid] = ar2[tid]; }
    __syncthreads();

    int lane = tid & 31;
    int w = blockIdx.x * 8 + (tid >> 5);
    if (w >= N_NODES) return;
    const float* h = g_h1 + (size_t)w * F1T;
    float acc = 0.f;
    #pragma unroll 5
    for (int k = 0; k < F1T; k += 4) {
        float4 x = *(const float4*)&h[k];
        acc += x.x * sW[(k + 0) * C_OUT + lane];
        acc += x.y * sW[(k + 1) * C_OUT + lane];
        acc += x.z * sW[(k + 2) * C_OUT + lane];
        acc += x.w * sW[(k + 3) * C_OUT + lane];
    }
    g_z2[(size_t)w * C_OUT + lane] = acc;
    float el = warp_sum(acc * sal[lane]);
    float er = warp_sum(acc * sar[lane]);
    if (lane == 0) { g_el2[w] = el; g_er2[w] = er; }
}

// ---------------- layer-2 aggregation -> output (no max pass) ----------------
__global__ __launch_bounds__(256) void k_agg2(const float* __restrict__ b2,
                                              float* __restrict__ out) {
    int w = (blockIdx.x * 256 + threadIdx.x) >> 5;
    if (w >= N_NODES) return;
    int lane = threadIdx.x & 31;
    int beg = g_off[w], end = g_off[w + 1];
    float ern = g_er2[w];

    float d = 0.f;
    for (int i = beg + lane; i < end; i += 32)
        d += __expf(lrelu(g_el2[g_psrc[i]] + ern));
    d = warp_sum(d);
    float inv = d > 0.f ? 1.f / d : 0.f;

    float acc = 0.f;
    int i = beg;
    for (; i + 1 < end; i += 2) {
        int s0 = g_psrc[i], s1 = g_psrc[i + 1];
        float e0 = g_el2[s0], e1 = g_el2[s1];
        float v0 = g_z2[(size_t)s0 * C_OUT + lane];
        float v1 = g_z2[(size_t)s1 * C_OUT + lane];
        acc += v0 * (__expf(lrelu(e0 + ern)) * inv);
        acc += v1 * (__expf(lrelu(e1 + ern)) * inv);
    }
    if (i < end) {
        int s = g_psrc[i];
        float a = __expf(lrelu(g_el2[s] + ern)) * inv;
        acc += g_z2[(size_t)s * C_OUT + lane] * a;
    }
    out[(size_t)w * C_OUT + lane] = acc + b2[lane];
}

// ---------------- launch ----------------
extern "C" void kernel_launch(void* const* d_in, const int* in_sizes, int n_in,
                              void* d_out, int out_size) {
    const float* features = (const float*)d_in[0];
    const float* W1  = (const float*)d_in[1];
    const float* al1 = (const float*)d_in[2];
    const float* ar1 = (const float*)d_in[3];
    const float* b1  = (const float*)d_in[4];
    const float* W2  = (const float*)d_in[5];
    const float* al2 = (const float*)d_in[6];
    const float* ar2 = (const float*)d_in[7];
    const float* b2  = (const float*)d_in[8];
    const int*   src = (const int*)d_in[9];
    const int*   dst = (const int*)d_in[10];
    float* out = (float*)d_out;

    // CSR build (grouped by dst)
    k_zero_cnt<<<(N_NODES + 255) / 256, 256>>>();
    k_hist<<<N_EDGES / 256, 256>>>(dst);
    k_scan<<<1, 1024>>>();
    k_scatter<<<N_EDGES / 256, 256>>>(src, dst);

    // layer 1
    dim3 g1((N_NODES + G1_BM - 1) / G1_BM, (F1T + G1_BN - 1) / G1_BN);
    k_gemm1_tc<<<g1, 256>>>(features, W1);
    k_attn1<<<(N_NODES * 32 + 255) / 256, 256>>>(al1, ar1);
    k_agg1<<<N_NODES / 8, 256>>>(b1);

    // layer 2
    k_gemm2<<<N_NODES / 8, 256>>>(W2, al2, ar2);
    k_agg2<<<N_NODES / 8, 256>>>(b2, out);
}

// round 5
// speedup vs baseline: 1.2304x; 1.0805x over previous
#include <cuda_runtime.h>
#include <cuda_bf16.h>
#include <math.h>

#define N_NODES 50000
#define N_EDGES 1600000
#define F_IN    256
#define F1T     200   // H1*F1
#define NH1     2
#define C_OUT   32
#define NEG_SLOPE 0.2f

// ---------------- scratch (static device globals; no allocation) ----------------
__device__ int   g_cnt[N_NODES];
__device__ int   g_off[N_NODES + 1];
__device__ int   g_cur[N_NODES];
__device__ int   g_psrc[N_EDGES];            // src node of each edge, grouped by dst
__device__ float g_z1[(size_t)N_NODES * F1T];   // 40 MB
__device__ float g_el1[N_NODES * NH1];
__device__ float g_er1[N_NODES * NH1];
__device__ float g_h1[(size_t)N_NODES * F1T];   // 40 MB
__device__ float g_z2[(size_t)N_NODES * C_OUT]; // 6.4 MB
__device__ float g_el2[N_NODES];
__device__ float g_er2[N_NODES];

// ---------------- helpers ----------------
__device__ __forceinline__ float warp_sum(float v) {
    #pragma unroll
    for (int o = 16; o; o >>= 1) v += __shfl_xor_sync(0xffffffffu, v, o);
    return v;
}
__device__ __forceinline__ float lrelu(float x) { return x > 0.f ? x : NEG_SLOPE * x; }
__device__ __forceinline__ float elu1(float x)  { return x > 0.f ? x : (__expf(x) - 1.f); }
__device__ __forceinline__ unsigned tf32u(float x) {
    unsigned u;
    asm("cvt.rna.tf32.f32 %0, %1;" : "=r"(u) : "f"(x));
    return u;
}

__device__ __forceinline__ unsigned smem_u32(const void* p) {
    return (unsigned)__cvta_generic_to_shared(p);
}
__device__ __forceinline__ void cp_async16(void* dst_smem, const void* src_gmem) {
    asm volatile("cp.async.cg.shared.global [%0], [%1], 16;\n"
                 :: "r"(smem_u32(dst_smem)), "l"(src_gmem));
}
__device__ __forceinline__ void cp_commit() { asm volatile("cp.async.commit_group;\n"); }
template <int N>
__device__ __forceinline__ void cp_wait() { asm volatile("cp.async.wait_group %0;\n" :: "n"(N)); }

// ---------------- CSR build ----------------
__global__ void k_hist(const int* __restrict__ dst) {
    int e = blockIdx.x * blockDim.x + threadIdx.x;
    if (e < N_EDGES) atomicAdd(&g_cnt[dst[e]], 1);
}

__global__ void k_scan() {   // single block, 1024 threads
    const int T = 1024;
    const int CH = (N_NODES + T - 1) / T;  // 49
    int tid = threadIdx.x;
    int beg = tid * CH;
    int end = min(beg + CH, N_NODES);
    int s = 0;
    for (int i = beg; i < end; i++) s += g_cnt[i];

    __shared__ int warp_sums[32];
    int lane = tid & 31, wid = tid >> 5;
    int v = s;
    #pragma unroll
    for (int o = 1; o < 32; o <<= 1) {
        int t = __shfl_up_sync(0xffffffffu, v, o);
        if (lane >= o) v += t;
    }
    if (lane == 31) warp_sums[wid] = v;
    __syncthreads();
    if (wid == 0) {
        int w = warp_sums[lane];
        #pragma unroll
        for (int o = 1; o < 32; o <<= 1) {
            int t = __shfl_up_sync(0xffffffffu, w, o);
            if (lane >= o) w += t;
        }
        warp_sums[lane] = w;
    }
    __syncthreads();
    int excl = (v - s) + (wid > 0 ? warp_sums[wid - 1] : 0);
    int run = excl;
    for (int i = beg; i < end; i++) {
        int c = g_cnt[i];
        g_off[i] = run;
        g_cur[i] = run;
        run += c;
    }
    if (tid == T - 1) g_off[N_NODES] = run;
}

__global__ void k_scatter(const int* __restrict__ src, const int* __restrict__ dst) {
    int e = blockIdx.x * blockDim.x + threadIdx.x;
    if (e < N_EDGES) {
        int p = atomicAdd(&g_cur[dst[e]], 1);
        g_psrc[p] = src[e];
    }
}

// ---------------- GEMM1 (tf32 mma, cp.async double-buffered) ----------------
// z1 = features @ W1 : [50000,256] x [256,200]
#define G1_BM 128
#define G1_BN 64
#define G1_BK 32
#define G1_LDA 36                 // sA[m][k] row-major, pad 36 -> frag loads conflict-free
#define G1_LDB 72                 // sB[k][n], pad 72
#define A_STAGE (G1_BM * G1_LDA)  // 4608 floats
#define B_STAGE (G1_BK * G1_LDB)  // 2304 floats
#define G1_SMEM ((2 * A_STAGE + 2 * B_STAGE) * 4)   // 55296 bytes
#define G1_NIT  (F_IN / G1_BK)    // 8

__device__ __forceinline__ void mma_tf32(float* d, const unsigned* a, const unsigned* b) {
    asm volatile(
        "mma.sync.aligned.m16n8k8.row.col.f32.tf32.tf32.f32 "
        "{%0,%1,%2,%3}, {%4,%5,%6,%7}, {%8,%9}, {%0,%1,%2,%3};"
        : "+f"(d[0]), "+f"(d[1]), "+f"(d[2]), "+f"(d[3])
        : "r"(a[0]), "r"(a[1]), "r"(a[2]), "r"(a[3]), "r"(b[0]), "r"(b[1]));
}

__global__ __launch_bounds__(256) void k_gemm1_tc(const float* __restrict__ A,
                                                  const float* __restrict__ B) {
    extern __shared__ float smem[];
    float* sA = smem;                      // [2][128][36]
    float* sB = smem + 2 * A_STAGE;        // [2][32][72]

    int tid = threadIdx.x;
    int lane = tid & 31, wid = tid >> 5;
    int wm = wid & 3, wn = wid >> 2;       // 4 x 2 warp grid
    int bm = blockIdx.x * G1_BM, bn = blockIdx.y * G1_BN;
    int q = lane >> 2, r = lane & 3;

    // loader coords
    int am = tid >> 3;                     // A row base (0..31), + it*32
    int akc = (tid & 7) * 4;               // A k offset

    auto load_stage = [&](int st, int k0) {
        float* a_s = sA + st * A_STAGE;
        float* b_s = sB + st * B_STAGE;
        #pragma unroll
        for (int it = 0; it < 4; it++) {
            int m = am + it * 32;
            float* dstp = &a_s[m * G1_LDA + akc];
            if (bm + m < N_NODES)
                cp_async16(dstp, &A[(size_t)(bm + m) * F_IN + k0 + akc]);
            else
                *(float4*)dstp = make_float4(0.f, 0.f, 0.f, 0.f);
        }
        // B tile: 32 rows x 64 cols = 32x16 four-float chunks = 512 chunks
        #pragma unroll
        for (int it = 0; it < 2; it++) {
            int idx = tid + it * 256;       // 0..511
            int kk = idx >> 4;              // 0..31
            int nc = (idx & 15) * 4;        // 0..60
            float* dstp = &b_s[kk * G1_LDB + nc];
            if (bn + nc < F1T)
                cp_async16(dstp, &B[(size_t)(k0 + kk) * F1T + bn + nc]);
            else
                *(float4*)dstp = make_float4(0.f, 0.f, 0.f, 0.f);
        }
        cp_commit();
    };

    float acc[2][4][4] = {};

    load_stage(0, 0);

    #pragma unroll
    for (int it = 0; it < G1_NIT; it++) {
        if (it + 1 < G1_NIT) {
            load_stage((it + 1) & 1, (it + 1) * G1_BK);
            cp_wait<1>();
        } else {
            cp_wait<0>();
        }
        __syncthreads();

        const float* a_s = sA + (it & 1) * A_STAGE;
        const float* b_s = sB + (it & 1) * B_STAGE;

        #pragma unroll
        for (int k8 = 0; k8 < G1_BK / 8; k8++) {
            int kb = k8 * 8;
            unsigned af[2][4], bf[4][2];
            #pragma unroll
            for (int mt = 0; mt < 2; mt++) {
                int m0 = wm * 32 + mt * 16 + q;
                af[mt][0] = tf32u(a_s[m0 * G1_LDA + kb + r]);
                af[mt][1] = tf32u(a_s[(m0 + 8) * G1_LDA + kb + r]);
                af[mt][2] = tf32u(a_s[m0 * G1_LDA + kb + r + 4]);
                af[mt][3] = tf32u(a_s[(m0 + 8) * G1_LDA + kb + r + 4]);
            }
            #pragma unroll
            for (int nt = 0; nt < 4; nt++) {
                int n0 = wn * 32 + nt * 8 + q;
                bf[nt][0] = tf32u(b_s[(kb + r) * G1_LDB + n0]);
                bf[nt][1] = tf32u(b_s[(kb + r + 4) * G1_LDB + n0]);
            }
            #pragma unroll
            for (int mt = 0; mt < 2; mt++)
                #pragma unroll
                for (int nt = 0; nt < 4; nt++)
                    mma_tf32(acc[mt][nt], af[mt], bf[nt]);
        }
        __syncthreads();
    }

    #pragma unroll
    for (int mt = 0; mt < 2; mt++) {
        #pragma unroll
        for (int nt = 0; nt < 4; nt++) {
            int row = bm + wm * 32 + mt * 16 + q;
            int col = bn + wn * 32 + nt * 8 + 2 * r;
            if (col < F1T) {
                if (row < N_NODES) {
                    float* p = &g_z1[(size_t)row * F1T + col];
                    p[0] = acc[mt][nt][0];
                    p[1] = acc[mt][nt][1];
                }
                if (row + 8 < N_NODES) {
                    float* p = &g_z1[(size_t)(row + 8) * F1T + col];
                    p[0] = acc[mt][nt][2];
                    p[1] = acc[mt][nt][3];
                }
            }
        }
    }
}

// ---------------- attention coefficients, layer 1 ----------------
__global__ __launch_bounds__(256) void k_attn1(const float* __restrict__ al,
                                               const float* __restrict__ ar) {
    int w = (blockIdx.x * blockDim.x + threadIdx.x) >> 5;
    if (w >= N_NODES) return;
    int lane = threadIdx.x & 31;
    const float* z = g_z1 + (size_t)w * F1T;
    float e0l = 0.f, e0r = 0.f, e1l = 0.f, e1r = 0.f;
    for (int f = lane; f < F1T; f += 32) {
        float v = z[f];
        float a = al[f], rr = ar[f];
        if (f < 100) { e0l += v * a; e0r += v * rr; }
        else         { e1l += v * a; e1r += v * rr; }
    }
    e0l = warp_sum(e0l); e0r = warp_sum(e0r);
    e1l = warp_sum(e1l); e1r = warp_sum(e1r);
    if (lane == 0) {
        g_el1[2 * w] = e0l; g_el1[2 * w + 1] = e1l;
        g_er1[2 * w] = e0r; g_er1[2 * w + 1] = e1r;
    }
}

// ---------------- layer-1 aggregation: single pass, unnormalized weights ----------------
__global__ __launch_bounds__(256) void k_agg1(const float* __restrict__ b1) {
    int w = (blockIdx.x * 256 + threadIdx.x) >> 5;
    if (w >= N_NODES) return;
    int lane = threadIdx.x & 31;
    int beg = g_off[w], end = g_off[w + 1];
    float er0 = g_er1[2 * w], er1v = g_er1[2 * w + 1];

    float4 acc0 = make_float4(0.f, 0.f, 0.f, 0.f);
    float4 acc1 = make_float4(0.f, 0.f, 0.f, 0.f);
    float d0 = 0.f, d1 = 0.f;
    bool has2 = lane < 18;
    float selA = (lane < 25) ? 1.f : 0.f;   // head boundary at f=100 (4*25)

    int i = beg;
    for (; i + 1 < end; i += 2) {
        int s0 = g_psrc[i], s1 = g_psrc[i + 1];
        float2 ea = *(const float2*)&g_el1[2 * s0];
        float2 eb = *(const float2*)&g_el1[2 * s1];
        const float* zr0 = g_z1 + (size_t)s0 * F1T;
        const float* zr1 = g_z1 + (size_t)s1 * F1T;
        float4 va = *(const float4*)&zr0[4 * lane];
        float4 vb = *(const float4*)&zr1[4 * lane];
        float w0a = __expf(lrelu(ea.x + er0));
        float w1a = __expf(lrelu(ea.y + er1v));
        float w0b = __expf(lrelu(eb.x + er0));
        float w1b = __expf(lrelu(eb.y + er1v));
        d0 += w0a + w0b; d1 += w1a + w1b;
        float wa = selA * w0a + (1.f - selA) * w1a;
        float wb = selA * w0b + (1.f - selA) * w1b;
        acc0.x += va.x * wa + vb.x * wb;
        acc0.y += va.y * wa + vb.y * wb;
        acc0.z += va.z * wa + vb.z * wb;
        acc0.w += va.w * wa + vb.w * wb;
        if (has2) {
            float4 v2a = *(const float4*)&zr0[128 + 4 * lane];
            float4 v2b = *(const float4*)&zr1[128 + 4 * lane];
            acc1.x += v2a.x * w1a + v2b.x * w1b;
            acc1.y += v2a.y * w1a + v2b.y * w1b;
            acc1.z += v2a.z * w1a + v2b.z * w1b;
            acc1.w += v2a.w * w1a + v2b.w * w1b;
        }
    }
    if (i < end) {
        int s = g_psrc[i];
        float2 el = *(const float2*)&g_el1[2 * s];
        const float* zr = g_z1 + (size_t)s * F1T;
        float4 v = *(const float4*)&zr[4 * lane];
        float w0 = __expf(lrelu(el.x + er0));
        float w1 = __expf(lrelu(el.y + er1v));
        d0 += w0; d1 += w1;
        float ww = selA * w0 + (1.f - selA) * w1;
        acc0.x += v.x * ww; acc0.y += v.y * ww;
        acc0.z += v.z * ww; acc0.w += v.w * ww;
        if (has2) {
            float4 v2 = *(const float4*)&zr[128 + 4 * lane];
            acc1.x += v2.x * w1; acc1.y += v2.y * w1;
            acc1.z += v2.z * w1; acc1.w += v2.w * w1;
        }
    }

    float inv0 = d0 > 0.f ? 1.f / d0 : 0.f;
    float inv1 = d1 > 0.f ? 1.f / d1 : 0.f;
    float invA = selA * inv0 + (1.f - selA) * inv1;

    float* out = g_h1 + (size_t)w * F1T;
    float4 bb = *(const float4*)&b1[4 * lane];
    float4 o;
    o.x = elu1(acc0.x * invA + bb.x); o.y = elu1(acc0.y * invA + bb.y);
    o.z = elu1(acc0.z * invA + bb.z); o.w = elu1(acc0.w * invA + bb.w);
    *(float4*)&out[4 * lane] = o;
    if (has2) {
        float4 bb2 = *(const float4*)&b1[128 + 4 * lane];
        float4 o2;
        o2.x = elu1(acc1.x * inv1 + bb2.x); o2.y = elu1(acc1.y * inv1 + bb2.y);
        o2.z = elu1(acc1.z * inv1 + bb2.z); o2.w = elu1(acc1.w * inv1 + bb2.w);
        *(float4*)&out[128 + 4 * lane] = o2;
    }
}

// ---------------- GEMM2 + attn coefs layer 2 (grid-strided) ----------------
#define G2_BLOCKS 625
__global__ __launch_bounds__(256) void k_gemm2(const float* __restrict__ W2,
                                               const float* __restrict__ al2,
                                               const float* __restrict__ ar2) {
    __shared__ float sW[F1T * C_OUT];   // 25.6 KB
    __shared__ float sal[C_OUT], sar[C_OUT];
    int tid = threadIdx.x;
    for (int i = tid; i < F1T * C_OUT; i += 256) sW[i] = W2[i];
    if (tid < C_OUT) { sal[tid] = al2[tid]; sar[tid] = ar2[tid]; }
    __syncthreads();

    int lane = tid & 31, wid = tid >> 5;
    for (int w = blockIdx.x * 8 + wid; w < N_NODES; w += G2_BLOCKS * 8) {
        const float* h = g_h1 + (size_t)w * F1T;
        float acc = 0.f;
        #pragma unroll 5
        for (int k = 0; k < F1T; k += 4) {
            float4 x = *(const float4*)&h[k];
            acc += x.x * sW[(k + 0) * C_OUT + lane];
            acc += x.y * sW[(k + 1) * C_OUT + lane];
            acc += x.z * sW[(k + 2) * C_OUT + lane];
            acc += x.w * sW[(k + 3) * C_OUT + lane];
        }
        g_z2[(size_t)w * C_OUT + lane] = acc;
        float el = warp_sum(acc * sal[lane]);
        float er = warp_sum(acc * sar[lane]);
        if (lane == 0) { g_el2[w] = el; g_er2[w] = er; }
    }
}

// ---------------- layer-2 aggregation -> output (single pass) ----------------
__global__ __launch_bounds__(256) void k_agg2(const float* __restrict__ b2,
                                              float* __restrict__ out) {
    int w = (blockIdx.x * 256 + threadIdx.x) >> 5;
    if (w >= N_NODES) return;
    int lane = threadIdx.x & 31;
    int beg = g_off[w], end = g_off[w + 1];
    float ern = g_er2[w];

    float acc = 0.f, d = 0.f;
    int i = beg;
    for (; i + 1 < end; i += 2) {
        int s0 = g_psrc[i], s1 = g_psrc[i + 1];
        float e0 = g_el2[s0], e1 = g_el2[s1];
        float v0 = g_z2[(size_t)s0 * C_OUT + lane];
        float v1 = g_z2[(size_t)s1 * C_OUT + lane];
        float w0 = __expf(lrelu(e0 + ern));
        float w1 = __expf(lrelu(e1 + ern));
        d += w0 + w1;
        acc += v0 * w0 + v1 * w1;
    }
    if (i < end) {
        int s = g_psrc[i];
        float ww = __expf(lrelu(g_el2[s] + ern));
        d += ww;
        acc += g_z2[(size_t)s * C_OUT + lane] * ww;
    }
    float inv = d > 0.f ? 1.f / d : 0.f;
    out[(size_t)w * C_OUT + lane] = acc * inv + b2[lane];
}

// ---------------- launch ----------------
extern "C" void kernel_launch(void* const* d_in, const int* in_sizes, int n_in,
                              void* d_out, int out_size) {
    const float* features = (const float*)d_in[0];
    const float* W1  = (const float*)d_in[1];
    const float* al1 = (const float*)d_in[2];
    const float* ar1 = (const float*)d_in[3];
    const float* b1  = (const float*)d_in[4];
    const float* W2  = (const float*)d_in[5];
    const float* al2 = (const float*)d_in[6];
    const float* ar2 = (const float*)d_in[7];
    const float* b2  = (const float*)d_in[8];
    const int*   src = (const int*)d_in[9];
    const int*   dst = (const int*)d_in[10];
    float* out = (float*)d_out;

    // fork a side stream for the CSR build (graph-capture fork/join via events)
    cudaStream_t s2;
    cudaEvent_t ev_fork, ev_join;
    cudaStreamCreateWithFlags(&s2, cudaStreamNonBlocking);
    cudaEventCreateWithFlags(&ev_fork, cudaEventDisableTiming);
    cudaEventCreateWithFlags(&ev_join, cudaEventDisableTiming);

    void* cnt_ptr = nullptr;
    cudaGetSymbolAddress(&cnt_ptr, g_cnt);

    cudaEventRecord(ev_fork, 0);
    cudaStreamWaitEvent(s2, ev_fork, 0);

    // CSR chain on s2
    cudaMemsetAsync(cnt_ptr, 0, N_NODES * sizeof(int), s2);
    k_hist<<<N_EDGES / 256, 256, 0, s2>>>(dst);
    k_scan<<<1, 1024, 0, s2>>>();
    k_scatter<<<N_EDGES / 256, 256, 0, s2>>>(src, dst);
    cudaEventRecord(ev_join, s2);

    // GEMM1 + attn1 on main stream (independent of CSR)
    cudaFuncSetAttribute(k_gemm1_tc, cudaFuncAttributeMaxDynamicSharedMemorySize, G1_SMEM);
    dim3 g1((N_NODES + G1_BM - 1) / G1_BM, (F1T + G1_BN - 1) / G1_BN);
    k_gemm1_tc<<<g1, 256, G1_SMEM>>>(features, W1);
    k_attn1<<<(N_NODES * 32 + 255) / 256, 256>>>(al1, ar1);

    // join: aggregation needs both branches
    cudaStreamWaitEvent(0, ev_join, 0);
    k_agg1<<<N_NODES / 8, 256>>>(b1);

    // layer 2
    k_gemm2<<<G2_BLOCKS, 256>>>(W2, al2, ar2);
    k_agg2<<<N_NODES / 8, 256>>>(b2, out);
}

// round 7
// speedup vs baseline: 1.2403x; 1.0080x over previous
#include <cuda_runtime.h>
#include <cuda_bf16.h>
#include <math.h>

#define N_NODES 50000
#define N_EDGES 1600000
#define F_IN    256
#define F1T     200   // H1*F1
#define NH1     2
#define C_OUT   32
#define NEG_SLOPE 0.2f
#define FULLM   0xffffffffu

// ---------------- scratch (static device globals; no allocation) ----------------
__device__ int   g_cnt[N_NODES];
__device__ int   g_off[N_NODES + 1];
__device__ int   g_cur[N_NODES];
__device__ int   g_psrc[N_EDGES];            // src node of each edge, grouped by dst
__device__ float g_z1[(size_t)N_NODES * F1T];   // 40 MB
__device__ float g_el1[N_NODES * NH1];
__device__ float g_er1[N_NODES * NH1];
__device__ float g_h1[(size_t)N_NODES * F1T];   // 40 MB
__device__ float g_z2[(size_t)N_NODES * C_OUT]; // 6.4 MB
__device__ float g_el2[N_NODES];
__device__ float g_er2[N_NODES];

// ---------------- helpers ----------------
__device__ __forceinline__ float warp_sum(float v) {
    #pragma unroll
    for (int o = 16; o; o >>= 1) v += __shfl_xor_sync(FULLM, v, o);
    return v;
}
__device__ __forceinline__ float lrelu(float x) { return x > 0.f ? x : NEG_SLOPE * x; }
__device__ __forceinline__ float elu1(float x)  { return x > 0.f ? x : (__expf(x) - 1.f); }
__device__ __forceinline__ unsigned tf32u(float x) {
    unsigned u;
    asm("cvt.rna.tf32.f32 %0, %1;" : "=r"(u) : "f"(x));
    return u;
}

__device__ __forceinline__ unsigned smem_u32(const void* p) {
    return (unsigned)__cvta_generic_to_shared(p);
}
__device__ __forceinline__ void cp_async16(void* dst_smem, const void* src_gmem) {
    asm volatile("cp.async.cg.shared.global [%0], [%1], 16;\n"
                 :: "r"(smem_u32(dst_smem)), "l"(src_gmem));
}
__device__ __forceinline__ void cp_commit() { asm volatile("cp.async.commit_group;\n"); }
template <int N>
__device__ __forceinline__ void cp_wait() { asm volatile("cp.async.wait_group %0;\n" :: "n"(N)); }

// ---------------- CSR build ----------------
__global__ void k_hist(const int* __restrict__ dst) {
    int e = blockIdx.x * blockDim.x + threadIdx.x;
    if (e < N_EDGES) atomicAdd(&g_cnt[dst[e]], 1);
}

__global__ void k_scan() {   // single block, 1024 threads
    const int T = 1024;
    const int CH = (N_NODES + T - 1) / T;  // 49
    int tid = threadIdx.x;
    int beg = tid * CH;
    int end = min(beg + CH, N_NODES);
    int s = 0;
    for (int i = beg; i < end; i++) s += g_cnt[i];

    __shared__ int warp_sums[32];
    int lane = tid & 31, wid = tid >> 5;
    int v = s;
    #pragma unroll
    for (int o = 1; o < 32; o <<= 1) {
        int t = __shfl_up_sync(FULLM, v, o);
        if (lane >= o) v += t;
    }
    if (lane == 31) warp_sums[wid] = v;
    __syncthreads();
    if (wid == 0) {
        int w = warp_sums[lane];
        #pragma unroll
        for (int o = 1; o < 32; o <<= 1) {
            int t = __shfl_up_sync(FULLM, w, o);
            if (lane >= o) w += t;
        }
        warp_sums[lane] = w;
    }
    __syncthreads();
    int excl = (v - s) + (wid > 0 ? warp_sums[wid - 1] : 0);
    int run = excl;
    for (int i = beg; i < end; i++) {
        int c = g_cnt[i];
        g_off[i] = run;
        g_cur[i] = run;
        run += c;
    }
    if (tid == T - 1) g_off[N_NODES] = run;
}

__global__ void k_scatter(const int* __restrict__ src, const int* __restrict__ dst) {
    int e = blockIdx.x * blockDim.x + threadIdx.x;
    if (e < N_EDGES) {
        int p = atomicAdd(&g_cur[dst[e]], 1);
        g_psrc[p] = src[e];
    }
}

// ---------------- GEMM1 (tf32 mma, cp.async double-buffered) ----------------
#define G1_BM 128
#define G1_BN 64
#define G1_BK 32
#define G1_LDA 36
#define G1_LDB 72
#define A_STAGE (G1_BM * G1_LDA)
#define B_STAGE (G1_BK * G1_LDB)
#define G1_SMEM ((2 * A_STAGE + 2 * B_STAGE) * 4)   // 55296 bytes
#define G1_NIT  (F_IN / G1_BK)

__device__ __forceinline__ void mma_tf32(float* d, const unsigned* a, const unsigned* b) {
    asm volatile(
        "mma.sync.aligned.m16n8k8.row.col.f32.tf32.tf32.f32 "
        "{%0,%1,%2,%3}, {%4,%5,%6,%7}, {%8,%9}, {%0,%1,%2,%3};"
        : "+f"(d[0]), "+f"(d[1]), "+f"(d[2]), "+f"(d[3])
        : "r"(a[0]), "r"(a[1]), "r"(a[2]), "r"(a[3]), "r"(b[0]), "r"(b[1]));
}

__global__ __launch_bounds__(256) void k_gemm1_tc(const float* __restrict__ A,
                                                  const float* __restrict__ B) {
    extern __shared__ float smem[];
    float* sA = smem;                      // [2][128][36]
    float* sB = smem + 2 * A_STAGE;        // [2][32][72]

    int tid = threadIdx.x;
    int lane = tid & 31, wid = tid >> 5;
    int wm = wid & 3, wn = wid >> 2;
    int bm = blockIdx.x * G1_BM, bn = blockIdx.y * G1_BN;
    int q = lane >> 2, r = lane & 3;

    int am = tid >> 3;
    int akc = (tid & 7) * 4;

    auto load_stage = [&](int st, int k0) {
        float* a_s = sA + st * A_STAGE;
        float* b_s = sB + st * B_STAGE;
        #pragma unroll
        for (int it = 0; it < 4; it++) {
            int m = am + it * 32;
            float* dstp = &a_s[m * G1_LDA + akc];
            if (bm + m < N_NODES)
                cp_async16(dstp, &A[(size_t)(bm + m) * F_IN + k0 + akc]);
            else
                *(float4*)dstp = make_float4(0.f, 0.f, 0.f, 0.f);
        }
        #pragma unroll
        for (int it = 0; it < 2; it++) {
            int idx = tid + it * 256;
            int kk = idx >> 4;
            int nc = (idx & 15) * 4;
            float* dstp = &b_s[kk * G1_LDB + nc];
            if (bn + nc < F1T)
                cp_async16(dstp, &B[(size_t)(k0 + kk) * F1T + bn + nc]);
            else
                *(float4*)dstp = make_float4(0.f, 0.f, 0.f, 0.f);
        }
        cp_commit();
    };

    float acc[2][4][4] = {};

    load_stage(0, 0);

    #pragma unroll
    for (int it = 0; it < G1_NIT; it++) {
        if (it + 1 < G1_NIT) {
            load_stage((it + 1) & 1, (it + 1) * G1_BK);
            cp_wait<1>();
        } else {
            cp_wait<0>();
        }
        __syncthreads();

        const float* a_s = sA + (it & 1) * A_STAGE;
        const float* b_s = sB + (it & 1) * B_STAGE;

        #pragma unroll
        for (int k8 = 0; k8 < G1_BK / 8; k8++) {
            int kb = k8 * 8;
            unsigned af[2][4], bf[4][2];
            #pragma unroll
            for (int mt = 0; mt < 2; mt++) {
                int m0 = wm * 32 + mt * 16 + q;
                af[mt][0] = tf32u(a_s[m0 * G1_LDA + kb + r]);
                af[mt][1] = tf32u(a_s[(m0 + 8) * G1_LDA + kb + r]);
                af[mt][2] = tf32u(a_s[m0 * G1_LDA + kb + r + 4]);
                af[mt][3] = tf32u(a_s[(m0 + 8) * G1_LDA + kb + r + 4]);
            }
            #pragma unroll
            for (int nt = 0; nt < 4; nt++) {
                int n0 = wn * 32 + nt * 8 + q;
                bf[nt][0] = tf32u(b_s[(kb + r) * G1_LDB + n0]);
                bf[nt][1] = tf32u(b_s[(kb + r + 4) * G1_LDB + n0]);
            }
            #pragma unroll
            for (int mt = 0; mt < 2; mt++)
                #pragma unroll
                for (int nt = 0; nt < 4; nt++)
                    mma_tf32(acc[mt][nt], af[mt], bf[nt]);
        }
        __syncthreads();
    }

    #pragma unroll
    for (int mt = 0; mt < 2; mt++) {
        #pragma unroll
        for (int nt = 0; nt < 4; nt++) {
            int row = bm + wm * 32 + mt * 16 + q;
            int col = bn + wn * 32 + nt * 8 + 2 * r;
            if (col < F1T) {
                if (row < N_NODES) {
                    float* p = &g_z1[(size_t)row * F1T + col];
                    p[0] = acc[mt][nt][0];
                    p[1] = acc[mt][nt][1];
                }
                if (row + 8 < N_NODES) {
                    float* p = &g_z1[(size_t)(row + 8) * F1T + col];
                    p[0] = acc[mt][nt][2];
                    p[1] = acc[mt][nt][3];
                }
            }
        }
    }
}

// ---------------- attention coefficients, layer 1 ----------------
__global__ __launch_bounds__(256) void k_attn1(const float* __restrict__ al,
                                               const float* __restrict__ ar) {
    int w = (blockIdx.x * blockDim.x + threadIdx.x) >> 5;
    if (w >= N_NODES) return;
    int lane = threadIdx.x & 31;
    const float* z = g_z1 + (size_t)w * F1T;
    float e0l = 0.f, e0r = 0.f, e1l = 0.f, e1r = 0.f;
    for (int f = lane; f < F1T; f += 32) {
        float v = z[f];
        float a = al[f], rr = ar[f];
        if (f < 100) { e0l += v * a; e0r += v * rr; }
        else         { e1l += v * a; e1r += v * rr; }
    }
    e0l = warp_sum(e0l); e0r = warp_sum(e0r);
    e1l = warp_sum(e1l); e1r = warp_sum(e1r);
    if (lane == 0) {
        g_el1[2 * w] = e0l; g_el1[2 * w + 1] = e1l;
        g_er1[2 * w] = e0r; g_er1[2 * w + 1] = e1r;
    }
}

// ---------------- layer-1 aggregation: chunked indices + shfl broadcast ----------------
__global__ __launch_bounds__(256) void k_agg1(const float* __restrict__ b1) {
    int w = (blockIdx.x * 256 + threadIdx.x) >> 5;
    if (w >= N_NODES) return;
    int lane = threadIdx.x & 31;
    int beg = g_off[w], end = g_off[w + 1];
    float er0 = g_er1[2 * w], er1v = g_er1[2 * w + 1];

    float4 acc0 = make_float4(0.f, 0.f, 0.f, 0.f);
    float4 acc1 = make_float4(0.f, 0.f, 0.f, 0.f);
    float d0 = 0.f, d1 = 0.f;
    bool has2 = lane < 18;
    float selA = (lane < 25) ? 1.f : 0.f;   // head boundary at f=100 (4*25)

    for (int base = beg; base < end; base += 32) {
        int n = min(32, end - base);
        // per-lane: one edge's index + weights (coalesced psrc, 1 exp pair per edge)
        int   s_l = 0;
        float w0_l = 0.f, w1_l = 0.f;
        if (lane < n) {
            s_l = g_psrc[base + lane];
            float2 el = *(const float2*)&g_el1[2 * s_l];
            w0_l = __expf(lrelu(el.x + er0));
            w1_l = __expf(lrelu(el.y + er1v));
        }
        d0 += w0_l; d1 += w1_l;    // per-lane partial; reduced once at the end

        int j = 0;
        for (; j + 4 <= n; j += 4) {
            int   ss[4];
            float w0s[4], w1s[4];
            #pragma unroll
            for (int u = 0; u < 4; u++) {
                ss[u]  = __shfl_sync(FULLM, s_l, j + u);
                w0s[u] = __shfl_sync(FULLM, w0_l, j + u);
                w1s[u] = __shfl_sync(FULLM, w1_l, j + u);
            }
            float4 v[4], v2[4];
            #pragma unroll
            for (int u = 0; u < 4; u++) {
                const float* zr = g_z1 + (size_t)ss[u] * F1T;
                v[u] = *(const float4*)&zr[4 * lane];
                if (has2) v2[u] = *(const float4*)&zr[128 + 4 * lane];
            }
            #pragma unroll
            for (int u = 0; u < 4; u++) {
                float ww = selA * w0s[u] + (1.f - selA) * w1s[u];
                acc0.x += v[u].x * ww; acc0.y += v[u].y * ww;
                acc0.z += v[u].z * ww; acc0.w += v[u].w * ww;
                if (has2) {
                    acc1.x += v2[u].x * w1s[u]; acc1.y += v2[u].y * w1s[u];
                    acc1.z += v2[u].z * w1s[u]; acc1.w += v2[u].w * w1s[u];
                }
            }
        }
        for (; j < n; j++) {
            int   s  = __shfl_sync(FULLM, s_l, j);
            float w0 = __shfl_sync(FULLM, w0_l, j);
            float w1 = __shfl_sync(FULLM, w1_l, j);
            const float* zr = g_z1 + (size_t)s * F1T;
            float4 v = *(const float4*)&zr[4 * lane];
            float ww = selA * w0 + (1.f - selA) * w1;
            acc0.x += v.x * ww; acc0.y += v.y * ww;
            acc0.z += v.z * ww; acc0.w += v.w * ww;
            if (has2) {
                float4 v2 = *(const float4*)&zr[128 + 4 * lane];
                acc1.x += v2.x * w1; acc1.y += v2.y * w1;
                acc1.z += v2.z * w1; acc1.w += v2.w * w1;
            }
        }
    }

    d0 = warp_sum(d0); d1 = warp_sum(d1);
    float inv0 = d0 > 0.f ? 1.f / d0 : 0.f;
    float inv1 = d1 > 0.f ? 1.f / d1 : 0.f;
    float invA = selA * inv0 + (1.f - selA) * inv1;

    float* out = g_h1 + (size_t)w * F1T;
    float4 bb = *(const float4*)&b1[4 * lane];
    float4 o;
    o.x = elu1(acc0.x * invA + bb.x); o.y = elu1(acc0.y * invA + bb.y);
    o.z = elu1(acc0.z * invA + bb.z); o.w = elu1(acc0.w * invA + bb.w);
    *(float4*)&out[4 * lane] = o;
    if (has2) {
        float4 bb2 = *(const float4*)&b1[128 + 4 * lane];
        float4 o2;
        o2.x = elu1(acc1.x * inv1 + bb2.x); o2.y = elu1(acc1.y * inv1 + bb2.y);
        o2.z = elu1(acc1.z * inv1 + bb2.z); o2.w = elu1(acc1.w * inv1 + bb2.w);
        *(float4*)&out[128 + 4 * lane] = o2;
    }
}

// ---------------- GEMM2 + attn coefs layer 2 (grid-strided) ----------------
#define G2_BLOCKS 625
__global__ __launch_bounds__(256) void k_gemm2(const float* __restrict__ W2,
                                               const float* __restrict__ al2,
                                               const float* __restrict__ ar2) {
    __shared__ float sW[F1T * C_OUT];   // 25.6 KB
    __shared__ float sal[C_OUT], sar[C_OUT];
    int tid = threadIdx.x;
    for (int i = tid; i < F1T * C_OUT; i += 256) sW[i] = W2[i];
    if (tid < C_OUT) { sal[tid] = al2[tid]; sar[tid] = ar2[tid]; }
    __syncthreads();

    int lane = tid & 31, wid = tid >> 5;
    for (int w = blockIdx.x * 8 + wid; w < N_NODES; w += G2_BLOCKS * 8) {
        const float* h = g_h1 + (size_t)w * F1T;
        float acc = 0.f;
        #pragma unroll 5
        for (int k = 0; k < F1T; k += 4) {
            float4 x = *(const float4*)&h[k];
            acc += x.x * sW[(k + 0) * C_OUT + lane];
            acc += x.y * sW[(k + 1) * C_OUT + lane];
            acc += x.z * sW[(k + 2) * C_OUT + lane];
            acc += x.w * sW[(k + 3) * C_OUT + lane];
        }
        g_z2[(size_t)w * C_OUT + lane] = acc;
        float el = warp_sum(acc * sal[lane]);
        float er = warp_sum(acc * sar[lane]);
        if (lane == 0) { g_el2[w] = el; g_er2[w] = er; }
    }
}

// ---------------- layer-2 aggregation -> output (chunked + shfl) ----------------
__global__ __launch_bounds__(256) void k_agg2(const float* __restrict__ b2,
                                              float* __restrict__ out) {
    int w = (blockIdx.x * 256 + threadIdx.x) >> 5;
    if (w >= N_NODES) return;
    int lane = threadIdx.x & 31;
    int beg = g_off[w], end = g_off[w + 1];
    float ern = g_er2[w];

    float acc = 0.f, d = 0.f;
    for (int base = beg; base < end; base += 32) {
        int n = min(32, end - base);
        int   s_l = 0;
        float w_l = 0.f;
        if (lane < n) {
            s_l = g_psrc[base + lane];
            w_l = __expf(lrelu(g_el2[s_l] + ern));
        }
        d += w_l;

        int j = 0;
        for (; j + 4 <= n; j += 4) {
            int   ss[4];
            float ws[4], vs[4];
            #pragma unroll
            for (int u = 0; u < 4; u++) {
                ss[u] = __shfl_sync(FULLM, s_l, j + u);
                ws[u] = __shfl_sync(FULLM, w_l, j + u);
            }
            #pragma unroll
            for (int u = 0; u < 4; u++)
                vs[u] = g_z2[(size_t)ss[u] * C_OUT + lane];
            #pragma unroll
            for (int u = 0; u < 4; u++)
                acc += vs[u] * ws[u];
        }
        for (; j < n; j++) {
            int   s  = __shfl_sync(FULLM, s_l, j);
            float ww = __shfl_sync(FULLM, w_l, j);
            acc += g_z2[(size_t)s * C_OUT + lane] * ww;
        }
    }

    d = warp_sum(d);
    float inv = d > 0.f ? 1.f / d : 0.f;
    out[(size_t)w * C_OUT + lane] = acc * inv + b2[lane];
}

// ---------------- launch ----------------
extern "C" void kernel_launch(void* const* d_in, const int* in_sizes, int n_in,
                              void* d_out, int out_size) {
    const float* features = (const float*)d_in[0];
    const float* W1  = (const float*)d_in[1];
    const float* al1 = (const float*)d_in[2];
    const float* ar1 = (const float*)d_in[3];
    const float* b1  = (const float*)d_in[4];
    const float* W2  = (const float*)d_in[5];
    const float* al2 = (const float*)d_in[6];
    const float* ar2 = (const float*)d_in[7];
    const float* b2  = (const float*)d_in[8];
    const int*   src = (const int*)d_in[9];
    const int*   dst = (const int*)d_in[10];
    float* out = (float*)d_out;

    // fork-stream resources: created once, reused across calls (host-side only)
    static cudaStream_t s2 = nullptr;
    static cudaEvent_t ev_fork = nullptr, ev_join = nullptr;
    static void* cnt_ptr = nullptr;
    if (!s2) {
        cudaStreamCreateWithFlags(&s2, cudaStreamNonBlocking);
        cudaEventCreateWithFlags(&ev_fork, cudaEventDisableTiming);
        cudaEventCreateWithFlags(&ev_join, cudaEventDisableTiming);
        cudaGetSymbolAddress(&cnt_ptr, g_cnt);
        cudaFuncSetAttribute(k_gemm1_tc, cudaFuncAttributeMaxDynamicSharedMemorySize, G1_SMEM);
    }

    cudaEventRecord(ev_fork, 0);
    cudaStreamWaitEvent(s2, ev_fork, 0);

    // CSR chain on s2
    cudaMemsetAsync(cnt_ptr, 0, N_NODES * sizeof(int), s2);
    k_hist<<<N_EDGES / 256, 256, 0, s2>>>(dst);
    k_scan<<<1, 1024, 0, s2>>>();
    k_scatter<<<N_EDGES / 256, 256, 0, s2>>>(src, dst);
    cudaEventRecord(ev_join, s2);

    // GEMM1 + attn1 on main stream (independent of CSR)
    dim3 g1((N_NODES + G1_BM - 1) / G1_BM, (F1T + G1_BN - 1) / G1_BN);
    k_gemm1_tc<<<g1, 256, G1_SMEM>>>(features, W1);
    k_attn1<<<(N_NODES * 32 + 255) / 256, 256>>>(al1, ar1);

    // join: aggregation needs both branches
    cudaStreamWaitEvent(0, ev_join, 0);
    k_agg1<<<N_NODES / 8, 256>>>(b1);

    // layer 2
    k_gemm2<<<G2_BLOCKS, 256>>>(W2, al2, ar2);
    k_agg2<<<N_NODES / 8, 256>>>(b2, out);
}

// round 8
// speedup vs baseline: 1.3981x; 1.1273x over previous
#include <cuda_runtime.h>
#include <cuda_fp16.h>
#include <math.h>

#define N_NODES 50000
#define N_EDGES 1600000
#define F_IN    256
#define F1T     200   // H1*F1
#define NH1     2
#define C_OUT   32
#define NEG_SLOPE 0.2f
#define FULLM   0xffffffffu

// ---------------- scratch (static device globals; no allocation) ----------------
__device__ int    g_cnt[N_NODES];
__device__ int    g_off[N_NODES + 1];
__device__ int    g_cur[N_NODES];
__device__ int    g_psrc[N_EDGES];               // src node per edge, grouped by dst
__device__ __half g_z1h[(size_t)N_NODES * F1T];  // 20 MB (fp16 z1)
__device__ float  g_wl[F_IN * 4];                // W1^T @ [al0|al1|ar0|ar1]
__device__ float  g_el1[N_NODES * NH1];
__device__ float  g_er1[N_NODES * NH1];
__device__ __half g_z2h[(size_t)N_NODES * C_OUT]; // 3.2 MB (fp16 z2)
__device__ float  g_el2[N_NODES];
__device__ float  g_er2[N_NODES];

// ---------------- helpers ----------------
__device__ __forceinline__ float warp_sum(float v) {
    #pragma unroll
    for (int o = 16; o; o >>= 1) v += __shfl_xor_sync(FULLM, v, o);
    return v;
}
__device__ __forceinline__ float lrelu(float x) { return x > 0.f ? x : NEG_SLOPE * x; }
__device__ __forceinline__ float elu1(float x)  { return x > 0.f ? x : (__expf(x) - 1.f); }
__device__ __forceinline__ unsigned tf32u(float x) {
    unsigned u;
    asm("cvt.rna.tf32.f32 %0, %1;" : "=r"(u) : "f"(x));
    return u;
}
// load 4 consecutive halfs -> float4 (8B aligned)
__device__ __forceinline__ float4 ld_half4(const __half* p) {
    uint2 raw = *(const uint2*)p;
    __half2 h0 = *reinterpret_cast<__half2*>(&raw.x);
    __half2 h1 = *reinterpret_cast<__half2*>(&raw.y);
    float2 f0 = __half22float2(h0), f1 = __half22float2(h1);
    return make_float4(f0.x, f0.y, f1.x, f1.y);
}

__device__ __forceinline__ unsigned smem_u32(const void* p) {
    return (unsigned)__cvta_generic_to_shared(p);
}
__device__ __forceinline__ void cp_async16(void* dst_smem, const void* src_gmem) {
    asm volatile("cp.async.cg.shared.global [%0], [%1], 16;\n"
                 :: "r"(smem_u32(dst_smem)), "l"(src_gmem));
}
__device__ __forceinline__ void cp_commit() { asm volatile("cp.async.commit_group;\n"); }
template <int N>
__device__ __forceinline__ void cp_wait() { asm volatile("cp.async.wait_group %0;\n" :: "n"(N)); }

// ---------------- CSR build ----------------
__global__ void k_hist(const int* __restrict__ dst) {
    int e = blockIdx.x * blockDim.x + threadIdx.x;
    if (e < N_EDGES) atomicAdd(&g_cnt[dst[e]], 1);
}

__global__ void k_scan() {   // single block, 1024 threads
    const int T = 1024;
    const int CH = (N_NODES + T - 1) / T;  // 49
    int tid = threadIdx.x;
    int beg = tid * CH;
    int end = min(beg + CH, N_NODES);
    int s = 0;
    for (int i = beg; i < end; i++) s += g_cnt[i];

    __shared__ int warp_sums[32];
    int lane = tid & 31, wid = tid >> 5;
    int v = s;
    #pragma unroll
    for (int o = 1; o < 32; o <<= 1) {
        int t = __shfl_up_sync(FULLM, v, o);
        if (lane >= o) v += t;
    }
    if (lane == 31) warp_sums[wid] = v;
    __syncthreads();
    if (wid == 0) {
        int w = warp_sums[lane];
        #pragma unroll
        for (int o = 1; o < 32; o <<= 1) {
            int t = __shfl_up_sync(FULLM, w, o);
            if (lane >= o) w += t;
        }
        warp_sums[lane] = w;
    }
    __syncthreads();
    int excl = (v - s) + (wid > 0 ? warp_sums[wid - 1] : 0);
    int run = excl;
    for (int i = beg; i < end; i++) {
        int c = g_cnt[i];
        g_off[i] = run;
        g_cur[i] = run;
        run += c;
    }
    if (tid == T - 1) g_off[N_NODES] = run;
}

__global__ void k_scatter(const int* __restrict__ src, const int* __restrict__ dst) {
    int e = blockIdx.x * blockDim.x + threadIdx.x;
    if (e < N_EDGES) {
        int p = atomicAdd(&g_cur[dst[e]], 1);
        g_psrc[p] = src[e];
    }
}

// ---------------- attention coef factorization: wl = W1^T @ [al|ar] ----------------
__global__ void k_wlprep(const float* __restrict__ W1,
                         const float* __restrict__ al,
                         const float* __restrict__ ar) {
    int k = threadIdx.x;          // 256 threads, 1 block
    const float* row = W1 + (size_t)k * F1T;
    float s0 = 0.f, s1 = 0.f, s2 = 0.f, s3 = 0.f;
    #pragma unroll 4
    for (int c = 0; c < 100; c++) {
        float w = row[c];
        s0 += w * al[c]; s2 += w * ar[c];
    }
    #pragma unroll 4
    for (int c = 100; c < 200; c++) {
        float w = row[c];
        s1 += w * al[c]; s3 += w * ar[c];
    }
    g_wl[k * 4 + 0] = s0; g_wl[k * 4 + 1] = s1;
    g_wl[k * 4 + 2] = s2; g_wl[k * 4 + 3] = s3;
}

// el1/er1 = features @ wl  (exact fp32; one warp per node)
__global__ __launch_bounds__(256) void k_attn1v(const float* __restrict__ X) {
    __shared__ float swl[F_IN * 4];
    int tid = threadIdx.x;
    *(float4*)&swl[tid * 4] = *(const float4*)&g_wl[tid * 4];
    __syncthreads();

    int lane = tid & 31;
    int w = blockIdx.x * 8 + (tid >> 5);
    if (w >= N_NODES) return;
    const float* x = X + (size_t)w * F_IN;
    float a0 = 0.f, a1 = 0.f, a2 = 0.f, a3 = 0.f;
    #pragma unroll
    for (int i = 0; i < 8; i++) {
        int k = lane + 32 * i;
        float xv = x[k];
        float4 wv = *(const float4*)&swl[k * 4];
        a0 += xv * wv.x; a1 += xv * wv.y;
        a2 += xv * wv.z; a3 += xv * wv.w;
    }
    a0 = warp_sum(a0); a1 = warp_sum(a1);
    a2 = warp_sum(a2); a3 = warp_sum(a3);
    if (lane == 0) {
        g_el1[2 * w] = a0; g_el1[2 * w + 1] = a1;
        g_er1[2 * w] = a2; g_er1[2 * w + 1] = a3;
    }
}

// ---------------- GEMM1 (tf32 mma, cp.async double-buffered) -> z1 fp16 ----------------
#define G1_BM 128
#define G1_BN 64
#define G1_BK 32
#define G1_LDA 36
#define G1_LDB 72
#define A_STAGE (G1_BM * G1_LDA)
#define B_STAGE (G1_BK * G1_LDB)
#define G1_SMEM ((2 * A_STAGE + 2 * B_STAGE) * 4)   // 55296 bytes
#define G1_NIT  (F_IN / G1_BK)

__device__ __forceinline__ void mma_tf32(float* d, const unsigned* a, const unsigned* b) {
    asm volatile(
        "mma.sync.aligned.m16n8k8.row.col.f32.tf32.tf32.f32 "
        "{%0,%1,%2,%3}, {%4,%5,%6,%7}, {%8,%9}, {%0,%1,%2,%3};"
        : "+f"(d[0]), "+f"(d[1]), "+f"(d[2]), "+f"(d[3])
        : "r"(a[0]), "r"(a[1]), "r"(a[2]), "r"(a[3]), "r"(b[0]), "r"(b[1]));
}

__global__ __launch_bounds__(256) void k_gemm1_tc(const float* __restrict__ A,
                                                  const float* __restrict__ B) {
    extern __shared__ float smem[];
    float* sA = smem;                      // [2][128][36]
    float* sB = smem + 2 * A_STAGE;        // [2][32][72]

    int tid = threadIdx.x;
    int lane = tid & 31, wid = tid >> 5;
    int wm = wid & 3, wn = wid >> 2;
    int bm = blockIdx.x * G1_BM, bn = blockIdx.y * G1_BN;
    int q = lane >> 2, r = lane & 3;

    int am = tid >> 3;
    int akc = (tid & 7) * 4;

    auto load_stage = [&](int st, int k0) {
        float* a_s = sA + st * A_STAGE;
        float* b_s = sB + st * B_STAGE;
        #pragma unroll
        for (int it = 0; it < 4; it++) {
            int m = am + it * 32;
            float* dstp = &a_s[m * G1_LDA + akc];
            if (bm + m < N_NODES)
                cp_async16(dstp, &A[(size_t)(bm + m) * F_IN + k0 + akc]);
            else
                *(float4*)dstp = make_float4(0.f, 0.f, 0.f, 0.f);
        }
        #pragma unroll
        for (int it = 0; it < 2; it++) {
            int idx = tid + it * 256;
            int kk = idx >> 4;
            int nc = (idx & 15) * 4;
            float* dstp = &b_s[kk * G1_LDB + nc];
            if (bn + nc < F1T)
                cp_async16(dstp, &B[(size_t)(k0 + kk) * F1T + bn + nc]);
            else
                *(float4*)dstp = make_float4(0.f, 0.f, 0.f, 0.f);
        }
        cp_commit();
    };

    float acc[2][4][4] = {};

    load_stage(0, 0);

    #pragma unroll
    for (int it = 0; it < G1_NIT; it++) {
        if (it + 1 < G1_NIT) {
            load_stage((it + 1) & 1, (it + 1) * G1_BK);
            cp_wait<1>();
        } else {
            cp_wait<0>();
        }
        __syncthreads();

        const float* a_s = sA + (it & 1) * A_STAGE;
        const float* b_s = sB + (it & 1) * B_STAGE;

        #pragma unroll
        for (int k8 = 0; k8 < G1_BK / 8; k8++) {
            int kb = k8 * 8;
            unsigned af[2][4], bf[4][2];
            #pragma unroll
            for (int mt = 0; mt < 2; mt++) {
                int m0 = wm * 32 + mt * 16 + q;
                af[mt][0] = tf32u(a_s[m0 * G1_LDA + kb + r]);
                af[mt][1] = tf32u(a_s[(m0 + 8) * G1_LDA + kb + r]);
                af[mt][2] = tf32u(a_s[m0 * G1_LDA + kb + r + 4]);
                af[mt][3] = tf32u(a_s[(m0 + 8) * G1_LDA + kb + r + 4]);
            }
            #pragma unroll
            for (int nt = 0; nt < 4; nt++) {
                int n0 = wn * 32 + nt * 8 + q;
                bf[nt][0] = tf32u(b_s[(kb + r) * G1_LDB + n0]);
                bf[nt][1] = tf32u(b_s[(kb + r + 4) * G1_LDB + n0]);
            }
            #pragma unroll
            for (int mt = 0; mt < 2; mt++)
                #pragma unroll
                for (int nt = 0; nt < 4; nt++)
                    mma_tf32(acc[mt][nt], af[mt], bf[nt]);
        }
        __syncthreads();
    }

    // epilogue: store z1 as half2
    #pragma unroll
    for (int mt = 0; mt < 2; mt++) {
        #pragma unroll
        for (int nt = 0; nt < 4; nt++) {
            int row = bm + wm * 32 + mt * 16 + q;
            int col = bn + wn * 32 + nt * 8 + 2 * r;
            if (col < F1T) {
                if (row < N_NODES) {
                    __half2 hv = __floats2half2_rn(acc[mt][nt][0], acc[mt][nt][1]);
                    *(__half2*)&g_z1h[(size_t)row * F1T + col] = hv;
                }
                if (row + 8 < N_NODES) {
                    __half2 hv = __floats2half2_rn(acc[mt][nt][2], acc[mt][nt][3]);
                    *(__half2*)&g_z1h[(size_t)(row + 8) * F1T + col] = hv;
                }
            }
        }
    }
}

// ---------------- fused layer-1 aggregation + ELU + GEMM2 + attn2 coefs ----------------
#define AG_BLOCKS 625
__global__ __launch_bounds__(256) void k_agg1_g2(const float* __restrict__ b1,
                                                 const float* __restrict__ W2,
                                                 const float* __restrict__ al2,
                                                 const float* __restrict__ ar2) {
    __shared__ float sW[F1T * C_OUT];   // 25.6 KB, W2 row-major [k][c]
    __shared__ float sal[C_OUT], sar[C_OUT];
    __shared__ float sh[8][F1T];        // per-warp h row
    int tid = threadIdx.x;
    for (int i = tid; i < F1T * C_OUT; i += 256) sW[i] = W2[i];
    if (tid < C_OUT) { sal[tid] = al2[tid]; sar[tid] = ar2[tid]; }
    __syncthreads();

    int lane = tid & 31, wid = tid >> 5;
    bool has2 = lane < 18;
    float selA = (lane < 25) ? 1.f : 0.f;   // head boundary at f=100 (4*25)

    for (int w = blockIdx.x * 8 + wid; w < N_NODES; w += AG_BLOCKS * 8) {
        int beg = g_off[w], end = g_off[w + 1];
        float er0 = g_er1[2 * w], er1v = g_er1[2 * w + 1];

        float4 acc0 = make_float4(0.f, 0.f, 0.f, 0.f);
        float4 acc1 = make_float4(0.f, 0.f, 0.f, 0.f);
        float d0 = 0.f, d1 = 0.f;

        for (int base = beg; base < end; base += 32) {
            int n = min(32, end - base);
            int   s_l = 0;
            float w0_l = 0.f, w1_l = 0.f;
            if (lane < n) {
                s_l = g_psrc[base + lane];
                float2 el = *(const float2*)&g_el1[2 * s_l];
                w0_l = __expf(lrelu(el.x + er0));
                w1_l = __expf(lrelu(el.y + er1v));
            }
            d0 += w0_l; d1 += w1_l;

            int j = 0;
            for (; j + 4 <= n; j += 4) {
                int   ss[4];
                float w0s[4], w1s[4];
                #pragma unroll
                for (int u = 0; u < 4; u++) {
                    ss[u]  = __shfl_sync(FULLM, s_l, j + u);
                    w0s[u] = __shfl_sync(FULLM, w0_l, j + u);
                    w1s[u] = __shfl_sync(FULLM, w1_l, j + u);
                }
                float4 v[4], v2[4];
                #pragma unroll
                for (int u = 0; u < 4; u++) {
                    const __half* zr = g_z1h + (size_t)ss[u] * F1T;
                    v[u] = ld_half4(zr + 4 * lane);
                    if (has2) v2[u] = ld_half4(zr + 128 + 4 * lane);
                }
                #pragma unroll
                for (int u = 0; u < 4; u++) {
                    float ww = selA * w0s[u] + (1.f - selA) * w1s[u];
                    acc0.x += v[u].x * ww; acc0.y += v[u].y * ww;
                    acc0.z += v[u].z * ww; acc0.w += v[u].w * ww;
                    if (has2) {
                        acc1.x += v2[u].x * w1s[u]; acc1.y += v2[u].y * w1s[u];
                        acc1.z += v2[u].z * w1s[u]; acc1.w += v2[u].w * w1s[u];
                    }
                }
            }
            for (; j < n; j++) {
                int   s  = __shfl_sync(FULLM, s_l, j);
                float w0 = __shfl_sync(FULLM, w0_l, j);
                float w1 = __shfl_sync(FULLM, w1_l, j);
                const __half* zr = g_z1h + (size_t)s * F1T;
                float4 v = ld_half4(zr + 4 * lane);
                float ww = selA * w0 + (1.f - selA) * w1;
                acc0.x += v.x * ww; acc0.y += v.y * ww;
                acc0.z += v.z * ww; acc0.w += v.w * ww;
                if (has2) {
                    float4 v2 = ld_half4(zr + 128 + 4 * lane);
                    acc1.x += v2.x * w1; acc1.y += v2.y * w1;
                    acc1.z += v2.z * w1; acc1.w += v2.w * w1;
                }
            }
        }

        d0 = warp_sum(d0); d1 = warp_sum(d1);
        float inv0 = d0 > 0.f ? 1.f / d0 : 0.f;
        float inv1 = d1 > 0.f ? 1.f / d1 : 0.f;
        float invA = selA * inv0 + (1.f - selA) * inv1;

        // h = elu(acc/denom + b1) -> smem (never touches gmem)
        float4 bb = *(const float4*)&b1[4 * lane];
        float4 o;
        o.x = elu1(acc0.x * invA + bb.x); o.y = elu1(acc0.y * invA + bb.y);
        o.z = elu1(acc0.z * invA + bb.z); o.w = elu1(acc0.w * invA + bb.w);
        *(float4*)&sh[wid][4 * lane] = o;
        if (has2) {
            float4 bb2 = *(const float4*)&b1[128 + 4 * lane];
            float4 o2;
            o2.x = elu1(acc1.x * inv1 + bb2.x); o2.y = elu1(acc1.y * inv1 + bb2.y);
            o2.z = elu1(acc1.z * inv1 + bb2.z); o2.w = elu1(acc1.w * inv1 + bb2.w);
            *(float4*)&sh[wid][128 + 4 * lane] = o2;
        }
        __syncwarp();

        // z2[c] = h . W2[:,c]  (lane = c)
        float acc2 = 0.f;
        #pragma unroll 5
        for (int k = 0; k < F1T; k += 4) {
            float4 hv = *(const float4*)&sh[wid][k];
            acc2 += hv.x * sW[(k + 0) * C_OUT + lane];
            acc2 += hv.y * sW[(k + 1) * C_OUT + lane];
            acc2 += hv.z * sW[(k + 2) * C_OUT + lane];
            acc2 += hv.w * sW[(k + 3) * C_OUT + lane];
        }
        g_z2h[(size_t)w * C_OUT + lane] = __float2half(acc2);
        float el = warp_sum(acc2 * sal[lane]);
        float er = warp_sum(acc2 * sar[lane]);
        if (lane == 0) { g_el2[w] = el; g_er2[w] = er; }
        __syncwarp();
    }
}

// ---------------- layer-2 aggregation -> output ----------------
__global__ __launch_bounds__(256) void k_agg2(const float* __restrict__ b2,
                                              float* __restrict__ out) {
    int w = (blockIdx.x * 256 + threadIdx.x) >> 5;
    if (w >= N_NODES) return;
    int lane = threadIdx.x & 31;
    int beg = g_off[w], end = g_off[w + 1];
    float ern = g_er2[w];

    float acc = 0.f, d = 0.f;
    for (int base = beg; base < end; base += 32) {
        int n = min(32, end - base);
        int   s_l = 0;
        float w_l = 0.f;
        if (lane < n) {
            s_l = g_psrc[base + lane];
            w_l = __expf(lrelu(g_el2[s_l] + ern));
        }
        d += w_l;

        int j = 0;
        for (; j + 4 <= n; j += 4) {
            int   ss[4];
            float ws[4], vs[4];
            #pragma unroll
            for (int u = 0; u < 4; u++) {
                ss[u] = __shfl_sync(FULLM, s_l, j + u);
                ws[u] = __shfl_sync(FULLM, w_l, j + u);
            }
            #pragma unroll
            for (int u = 0; u < 4; u++)
                vs[u] = __half2float(g_z2h[(size_t)ss[u] * C_OUT + lane]);
            #pragma unroll
            for (int u = 0; u < 4; u++)
                acc += vs[u] * ws[u];
        }
        for (; j < n; j++) {
            int   s  = __shfl_sync(FULLM, s_l, j);
            float ww = __shfl_sync(FULLM, w_l, j);
            acc += __half2float(g_z2h[(size_t)s * C_OUT + lane]) * ww;
        }
    }

    d = warp_sum(d);
    float inv = d > 0.f ? 1.f / d : 0.f;
    out[(size_t)w * C_OUT + lane] = acc * inv + b2[lane];
}

// ---------------- launch ----------------
extern "C" void kernel_launch(void* const* d_in, const int* in_sizes, int n_in,
                              void* d_out, int out_size) {
    const float* features = (const float*)d_in[0];
    const float* W1  = (const float*)d_in[1];
    const float* al1 = (const float*)d_in[2];
    const float* ar1 = (const float*)d_in[3];
    const float* b1  = (const float*)d_in[4];
    const float* W2  = (const float*)d_in[5];
    const float* al2 = (const float*)d_in[6];
    const float* ar2 = (const float*)d_in[7];
    const float* b2  = (const float*)d_in[8];
    const int*   src = (const int*)d_in[9];
    const int*   dst = (const int*)d_in[10];
    float* out = (float*)d_out;

    // streams/events created once, reused (host-side only)
    static cudaStream_t s2 = nullptr, s3 = nullptr;
    static cudaEvent_t ev_fork = nullptr, ev_csr = nullptr, ev_attn = nullptr;
    static void* cnt_ptr = nullptr;
    if (!s2) {
        cudaStreamCreateWithFlags(&s2, cudaStreamNonBlocking);
        cudaStreamCreateWithFlags(&s3, cudaStreamNonBlocking);
        cudaEventCreateWithFlags(&ev_fork, cudaEventDisableTiming);
        cudaEventCreateWithFlags(&ev_csr, cudaEventDisableTiming);
        cudaEventCreateWithFlags(&ev_attn, cudaEventDisableTiming);
        cudaGetSymbolAddress(&cnt_ptr, g_cnt);
        cudaFuncSetAttribute(k_gemm1_tc, cudaFuncAttributeMaxDynamicSharedMemorySize, G1_SMEM);
    }

    cudaEventRecord(ev_fork, 0);
    cudaStreamWaitEvent(s2, ev_fork, 0);
    cudaStreamWaitEvent(s3, ev_fork, 0);

    // CSR chain on s2
    cudaMemsetAsync(cnt_ptr, 0, N_NODES * sizeof(int), s2);
    k_hist<<<N_EDGES / 256, 256, 0, s2>>>(dst);
    k_scan<<<1, 1024, 0, s2>>>();
    k_scatter<<<N_EDGES / 256, 256, 0, s2>>>(src, dst);
    cudaEventRecord(ev_csr, s2);

    // GEMM1 on main stream (kernel #4 in submission order -> ncu slot)
    dim3 g1((N_NODES + G1_BM - 1) / G1_BM, (F1T + G1_BN - 1) / G1_BN);
    k_gemm1_tc<<<g1, 256, G1_SMEM>>>(features, W1);

    // attention-coef GEMV chain on s3 (independent of gemm1/CSR)
    k_wlprep<<<1, 256, 0, s3>>>(W1, al1, ar1);
    k_attn1v<<<N_NODES / 8, 256, 0, s3>>>(features);
    cudaEventRecord(ev_attn, s3);

    // join: fused agg needs CSR + el/er + z1
    cudaStreamWaitEvent(0, ev_csr, 0);
    cudaStreamWaitEvent(0, ev_attn, 0);
    k_agg1_g2<<<AG_BLOCKS, 256>>>(b1, W2, al2, ar2);

    // layer-2 aggregation
    k_agg2<<<N_NODES / 8, 256>>>(b2, out);
}

// round 10
// speedup vs baseline: 1.6886x; 1.2078x over previous
#include <cuda_runtime.h>
#include <cuda_fp16.h>
#include <math.h>

#define N_NODES 50000
#define N_EDGES 1600000
#define F_IN    256
#define F1T     200   // H1*F1
#define NH1     2
#define C_OUT   32
#define NEG_SLOPE 0.2f
#define FULLM   0xffffffffu

// ---------------- scratch (static device globals; no allocation) ----------------
__device__ int    g_cnt[N_NODES];
__device__ int    g_off[N_NODES + 1];
__device__ int    g_cur[N_NODES];
__device__ int    g_done;                        // last-block flag for histscan
__device__ int    g_psrc[N_EDGES];               // src node per edge, grouped by dst
__device__ __half g_z1h[(size_t)N_NODES * F1T];  // 20 MB (fp16 z1)
__device__ float  g_el1[N_NODES * NH1];
__device__ float  g_er1[N_NODES * NH1];
__device__ __half g_z2h[(size_t)N_NODES * C_OUT]; // 3.2 MB (fp16 z2)
__device__ float  g_el2[N_NODES];
__device__ float  g_er2[N_NODES];

// ---------------- helpers ----------------
__device__ __forceinline__ float warp_sum(float v) {
    #pragma unroll
    for (int o = 16; o; o >>= 1) v += __shfl_xor_sync(FULLM, v, o);
    return v;
}
__device__ __forceinline__ float lrelu(float x) { return x > 0.f ? x : NEG_SLOPE * x; }
__device__ __forceinline__ float elu1(float x)  { return x > 0.f ? x : (__expf(x) - 1.f); }
__device__ __forceinline__ unsigned tf32u(float x) {
    unsigned u;
    asm("cvt.rna.tf32.f32 %0, %1;" : "=r"(u) : "f"(x));
    return u;
}
// load 4 consecutive halfs -> float4 (8B aligned)
__device__ __forceinline__ float4 ld_half4(const __half* p) {
    uint2 raw = *(const uint2*)p;
    __half2 h0 = *reinterpret_cast<__half2*>(&raw.x);
    __half2 h1 = *reinterpret_cast<__half2*>(&raw.y);
    float2 f0 = __half22float2(h0), f1 = __half22float2(h1);
    return make_float4(f0.x, f0.y, f1.x, f1.y);
}

__device__ __forceinline__ unsigned smem_u32(const void* p) {
    return (unsigned)__cvta_generic_to_shared(p);
}
__device__ __forceinline__ void cp_async16(void* dst_smem, const void* src_gmem) {
    asm volatile("cp.async.cg.shared.global [%0], [%1], 16;\n"
                 :: "r"(smem_u32(dst_smem)), "l"(src_gmem));
}
__device__ __forceinline__ void cp_commit() { asm volatile("cp.async.commit_group;\n"); }
template <int N>
__device__ __forceinline__ void cp_wait() { asm volatile("cp.async.wait_group %0;\n" :: "n"(N)); }

// ---------------- CSR build: fused hist + scan (last-block pattern) ----------------
#define HS_BLOCKS ((N_EDGES + 1023) / 1024)   // 1563
__global__ __launch_bounds__(1024) void k_histscan(const int* __restrict__ dst) {
    int tid = threadIdx.x;
    int e = blockIdx.x * 1024 + tid;
    if (e < N_EDGES) atomicAdd(&g_cnt[dst[e]], 1);

    // last finishing block runs the scan
    __threadfence();
    __shared__ int s_last;
    __syncthreads();
    if (tid == 0) s_last = (atomicAdd(&g_done, 1) == gridDim.x - 1);
    __syncthreads();
    if (!s_last) return;

    // exclusive scan over g_cnt (1024 threads, chunked)
    const int CH = (N_NODES + 1023) / 1024;  // 49
    int beg = tid * CH;
    int end = min(beg + CH, N_NODES);
    int s = 0;
    for (int i = beg; i < end; i++) s += g_cnt[i];

    __shared__ int warp_sums[32];
    int lane = tid & 31, wid = tid >> 5;
    int v = s;
    #pragma unroll
    for (int o = 1; o < 32; o <<= 1) {
        int t = __shfl_up_sync(FULLM, v, o);
        if (lane >= o) v += t;
    }
    if (lane == 31) warp_sums[wid] = v;
    __syncthreads();
    if (wid == 0) {
        int w = warp_sums[lane];
        #pragma unroll
        for (int o = 1; o < 32; o <<= 1) {
            int t = __shfl_up_sync(FULLM, w, o);
            if (lane >= o) w += t;
        }
        warp_sums[lane] = w;
    }
    __syncthreads();
    int excl = (v - s) + (wid > 0 ? warp_sums[wid - 1] : 0);
    int run = excl;
    for (int i = beg; i < end; i++) {
        int c = g_cnt[i];
        g_off[i] = run;
        g_cur[i] = run;
        run += c;
    }
    if (tid == 1023) g_off[N_NODES] = run;
    if (tid == 0) g_done = 0;   // reset for next replay
}

__global__ void k_scatter(const int* __restrict__ src, const int* __restrict__ dst) {
    int e = blockIdx.x * blockDim.x + threadIdx.x;
    if (e < N_EDGES) {
        int p = atomicAdd(&g_cur[dst[e]], 1);
        g_psrc[p] = src[e];
    }
}

// ---------------- GEMM1 (tf32 mma) -> z1 fp16, + fused attention coefs ----------------
#define G1_BM 128
#define G1_BN 64
#define G1_BK 32
#define G1_LDA 36
#define G1_LDB 72
#define A_STAGE (G1_BM * G1_LDA)
#define B_STAGE (G1_BK * G1_LDB)
#define G1_SMEM ((2 * A_STAGE + 2 * B_STAGE) * 4)   // 55296 bytes dynamic
#define G1_NIT  (F_IN / G1_BK)

__device__ __forceinline__ void mma_tf32(float* d, const unsigned* a, const unsigned* b) {
    asm volatile(
        "mma.sync.aligned.m16n8k8.row.col.f32.tf32.tf32.f32 "
        "{%0,%1,%2,%3}, {%4,%5,%6,%7}, {%8,%9}, {%0,%1,%2,%3};"
        : "+f"(d[0]), "+f"(d[1]), "+f"(d[2]), "+f"(d[3])
        : "r"(a[0]), "r"(a[1]), "r"(a[2]), "r"(a[3]), "r"(b[0]), "r"(b[1]));
}

__global__ __launch_bounds__(256) void k_gemm1_tc(const float* __restrict__ A,
                                                  const float* __restrict__ B,
                                                  const float* __restrict__ al1,
                                                  const float* __restrict__ ar1) {
    extern __shared__ float smem[];
    float* sA = smem;                      // [2][128][36]
    float* sB = smem + 2 * A_STAGE;        // [2][32][72]
    __shared__ float s_al[F1T], s_ar[F1T];

    int tid = threadIdx.x;
    int lane = tid & 31, wid = tid >> 5;
    int wm = wid & 3, wn = wid >> 2;
    int bm = blockIdx.x * G1_BM, bn = blockIdx.y * G1_BN;
    int q = lane >> 2, r = lane & 3;

    for (int i = tid; i < F1T; i += 256) { s_al[i] = al1[i]; s_ar[i] = ar1[i]; }

    int am = tid >> 3;
    int akc = (tid & 7) * 4;

    auto load_stage = [&](int st, int k0) {
        float* a_s = sA + st * A_STAGE;
        float* b_s = sB + st * B_STAGE;
        #pragma unroll
        for (int it = 0; it < 4; it++) {
            int m = am + it * 32;
            float* dstp = &a_s[m * G1_LDA + akc];
            if (bm + m < N_NODES)
                cp_async16(dstp, &A[(size_t)(bm + m) * F_IN + k0 + akc]);
            else
                *(float4*)dstp = make_float4(0.f, 0.f, 0.f, 0.f);
        }
        #pragma unroll
        for (int it = 0; it < 2; it++) {
            int idx = tid + it * 256;
            int kk = idx >> 4;
            int nc = (idx & 15) * 4;
            float* dstp = &b_s[kk * G1_LDB + nc];
            if (bn + nc < F1T)
                cp_async16(dstp, &B[(size_t)(k0 + kk) * F1T + bn + nc]);
            else
                *(float4*)dstp = make_float4(0.f, 0.f, 0.f, 0.f);
        }
        cp_commit();
    };

    float acc[2][4][4] = {};

    load_stage(0, 0);

    #pragma unroll
    for (int it = 0; it < G1_NIT; it++) {
        if (it + 1 < G1_NIT) {
            load_stage((it + 1) & 1, (it + 1) * G1_BK);
            cp_wait<1>();
        } else {
            cp_wait<0>();
        }
        __syncthreads();

        const float* a_s = sA + (it & 1) * A_STAGE;
        const float* b_s = sB + (it & 1) * B_STAGE;

        #pragma unroll
        for (int k8 = 0; k8 < G1_BK / 8; k8++) {
            int kb = k8 * 8;
            unsigned af[2][4], bf[4][2];
            #pragma unroll
            for (int mt = 0; mt < 2; mt++) {
                int m0 = wm * 32 + mt * 16 + q;
                af[mt][0] = tf32u(a_s[m0 * G1_LDA + kb + r]);
                af[mt][1] = tf32u(a_s[(m0 + 8) * G1_LDA + kb + r]);
                af[mt][2] = tf32u(a_s[m0 * G1_LDA + kb + r + 4]);
                af[mt][3] = tf32u(a_s[(m0 + 8) * G1_LDA + kb + r + 4]);
            }
            #pragma unroll
            for (int nt = 0; nt < 4; nt++) {
                int n0 = wn * 32 + nt * 8 + q;
                bf[nt][0] = tf32u(b_s[(kb + r) * G1_LDB + n0]);
                bf[nt][1] = tf32u(b_s[(kb + r + 4) * G1_LDB + n0]);
            }
            #pragma unroll
            for (int mt = 0; mt < 2; mt++)
                #pragma unroll
                for (int nt = 0; nt < 4; nt++)
                    mma_tf32(acc[mt][nt], af[mt], bf[nt]);
        }
        __syncthreads();
    }

    // epilogue A: store z1 as half2
    #pragma unroll
    for (int mt = 0; mt < 2; mt++) {
        #pragma unroll
        for (int nt = 0; nt < 4; nt++) {
            int row = bm + wm * 32 + mt * 16 + q;
            int col = bn + wn * 32 + nt * 8 + 2 * r;
            if (col < F1T) {
                if (row < N_NODES) {
                    __half2 hv = __floats2half2_rn(acc[mt][nt][0], acc[mt][nt][1]);
                    *(__half2*)&g_z1h[(size_t)row * F1T + col] = hv;
                }
                if (row + 8 < N_NODES) {
                    __half2 hv = __floats2half2_rn(acc[mt][nt][2], acc[mt][nt][3]);
                    *(__half2*)&g_z1h[(size_t)(row + 8) * F1T + col] = hv;
                }
            }
        }
    }

    // epilogue B: partial el/er per row (reduce over this thread's 8 cols,
    // then over the 4 lanes sharing q, then atomicAdd)
    #pragma unroll
    for (int mt = 0; mt < 2; mt++) {
        float e0l = 0.f, e1l = 0.f, e0r = 0.f, e1r = 0.f;   // row r0
        float f0l = 0.f, f1l = 0.f, f0r = 0.f, f1r = 0.f;   // row r0+8
        #pragma unroll
        for (int nt = 0; nt < 4; nt++) {
            int colb = bn + wn * 32 + nt * 8 + 2 * r;
            #pragma unroll
            for (int cc = 0; cc < 2; cc++) {
                int c = colb + cc;
                if (c < F1T) {
                    float a = s_al[c], rr = s_ar[c];
                    float zt = acc[mt][nt][cc];
                    float zb = acc[mt][nt][2 + cc];
                    if (c < 100) { e0l += zt * a; e0r += zt * rr; f0l += zb * a; f0r += zb * rr; }
                    else         { e1l += zt * a; e1r += zt * rr; f1l += zb * a; f1r += zb * rr; }
                }
            }
        }
        #pragma unroll
        for (int o = 1; o <= 2; o <<= 1) {
            e0l += __shfl_xor_sync(FULLM, e0l, o); e1l += __shfl_xor_sync(FULLM, e1l, o);
            e0r += __shfl_xor_sync(FULLM, e0r, o); e1r += __shfl_xor_sync(FULLM, e1r, o);
            f0l += __shfl_xor_sync(FULLM, f0l, o); f1l += __shfl_xor_sync(FULLM, f1l, o);
            f0r += __shfl_xor_sync(FULLM, f0r, o); f1r += __shfl_xor_sync(FULLM, f1r, o);
        }
        if (r == 0) {
            int row = bm + wm * 32 + mt * 16 + q;
            if (row < N_NODES) {
                atomicAdd(&g_el1[2 * row],     e0l); atomicAdd(&g_el1[2 * row + 1], e1l);
                atomicAdd(&g_er1[2 * row],     e0r); atomicAdd(&g_er1[2 * row + 1], e1r);
            }
            if (row + 8 < N_NODES) {
                atomicAdd(&g_el1[2 * (row + 8)],     f0l); atomicAdd(&g_el1[2 * (row + 8) + 1], f1l);
                atomicAdd(&g_er1[2 * (row + 8)],     f0r); atomicAdd(&g_er1[2 * (row + 8) + 1], f1r);
            }
        }
    }
}

// ---------------- fused layer-1 aggregation + ELU + GEMM2 + attn2 coefs ----------------
#define AG_BLOCKS 625
__global__ __launch_bounds__(256) void k_agg1_g2(const float* __restrict__ b1,
                                                 const float* __restrict__ W2,
                                                 const float* __restrict__ al2,
                                                 const float* __restrict__ ar2) {
    __shared__ float sW[F1T * C_OUT];   // 25.6 KB, W2 row-major [k][c]
    __shared__ float sal[C_OUT], sar[C_OUT];
    __shared__ float sh[8][F1T];        // per-warp h row
    int tid = threadIdx.x;
    for (int i = tid; i < F1T * C_OUT; i += 256) sW[i] = W2[i];
    if (tid < C_OUT) { sal[tid] = al2[tid]; sar[tid] = ar2[tid]; }
    __syncthreads();

    int lane = tid & 31, wid = tid >> 5;
    bool has2 = lane < 18;
    float selA = (lane < 25) ? 1.f : 0.f;   // head boundary at f=100 (4*25)

    for (int w = blockIdx.x * 8 + wid; w < N_NODES; w += AG_BLOCKS * 8) {
        int beg = g_off[w], end = g_off[w + 1];
        float er0 = g_er1[2 * w], er1v = g_er1[2 * w + 1];

        float4 acc0 = make_float4(0.f, 0.f, 0.f, 0.f);
        float4 acc1 = make_float4(0.f, 0.f, 0.f, 0.f);
        float d0 = 0.f, d1 = 0.f;

        for (int base = beg; base < end; base += 32) {
            int n = min(32, end - base);
            int   s_l = 0;
            float w0_l = 0.f, w1_l = 0.f;
            if (lane < n) {
                s_l = g_psrc[base + lane];
                float2 el = *(const float2*)&g_el1[2 * s_l];
                w0_l = __expf(lrelu(el.x + er0));
                w1_l = __expf(lrelu(el.y + er1v));
            }
            d0 += w0_l; d1 += w1_l;

            int j = 0;
            for (; j + 4 <= n; j += 4) {
                int   ss[4];
                float w0s[4], w1s[4];
                #pragma unroll
                for (int u = 0; u < 4; u++) {
                    ss[u]  = __shfl_sync(FULLM, s_l, j + u);
                    w0s[u] = __shfl_sync(FULLM, w0_l, j + u);
                    w1s[u] = __shfl_sync(FULLM, w1_l, j + u);
                }
                float4 v[4], v2[4];
                #pragma unroll
                for (int u = 0; u < 4; u++) {
                    const __half* zr = g_z1h + (size_t)ss[u] * F1T;
                    v[u] = ld_half4(zr + 4 * lane);
                    if (has2) v2[u] = ld_half4(zr + 128 + 4 * lane);
                }
                #pragma unroll
                for (int u = 0; u < 4; u++) {
                    float ww = selA * w0s[u] + (1.f - selA) * w1s[u];
                    acc0.x += v[u].x * ww; acc0.y += v[u].y * ww;
                    acc0.z += v[u].z * ww; acc0.w += v[u].w * ww;
                    if (has2) {
                        acc1.x += v2[u].x * w1s[u]; acc1.y += v2[u].y * w1s[u];
                        acc1.z += v2[u].z * w1s[u]; acc1.w += v2[u].w * w1s[u];
                    }
                }
            }
            for (; j < n; j++) {
                int   s  = __shfl_sync(FULLM, s_l, j);
                float w0 = __shfl_sync(FULLM, w0_l, j);
                float w1 = __shfl_sync(FULLM, w1_l, j);
                const __half* zr = g_z1h + (size_t)s * F1T;
                float4 v = ld_half4(zr + 4 * lane);
                float ww = selA * w0 + (1.f - selA) * w1;
                acc0.x += v.x * ww; acc0.y += v.y * ww;
                acc0.z += v.z * ww; acc0.w += v.w * ww;
                if (has2) {
                    float4 v2 = ld_half4(zr + 128 + 4 * lane);
                    acc1.x += v2.x * w1; acc1.y += v2.y * w1;
                    acc1.z += v2.z * w1; acc1.w += v2.w * w1;
                }
            }
        }

        d0 = warp_sum(d0); d1 = warp_sum(d1);
        float inv0 = d0 > 0.f ? 1.f / d0 : 0.f;
        float inv1 = d1 > 0.f ? 1.f / d1 : 0.f;
        float invA = selA * inv0 + (1.f - selA) * inv1;

        // h = elu(acc/denom + b1) -> smem (never touches gmem)
        float4 bb = *(const float4*)&b1[4 * lane];
        float4 o;
        o.x = elu1(acc0.x * invA + bb.x); o.y = elu1(acc0.y * invA + bb.y);
        o.z = elu1(acc0.z * invA + bb.z); o.w = elu1(acc0.w * invA + bb.w);
        *(float4*)&sh[wid][4 * lane] = o;
        if (has2) {
            float4 bb2 = *(const float4*)&b1[128 + 4 * lane];
            float4 o2;
            o2.x = elu1(acc1.x * inv1 + bb2.x); o2.y = elu1(acc1.y * inv1 + bb2.y);
            o2.z = elu1(acc1.z * inv1 + bb2.z); o2.w = elu1(acc1.w * inv1 + bb2.w);
            *(float4*)&sh[wid][128 + 4 * lane] = o2;
        }
        __syncwarp();

        // z2[c] = h . W2[:,c]  (lane = c)
        float acc2 = 0.f;
        #pragma unroll 5
        for (int k = 0; k < F1T; k += 4) {
            float4 hv = *(const float4*)&sh[wid][k];
            acc2 += hv.x * sW[(k + 0) * C_OUT + lane];
            acc2 += hv.y * sW[(k + 1) * C_OUT + lane];
            acc2 += hv.z * sW[(k + 2) * C_OUT + lane];
            acc2 += hv.w * sW[(k + 3) * C_OUT + lane];
        }
        g_z2h[(size_t)w * C_OUT + lane] = __float2half(acc2);
        float el = warp_sum(acc2 * sal[lane]);
        float er = warp_sum(acc2 * sar[lane]);
        if (lane == 0) { g_el2[w] = el; g_er2[w] = er; }
        __syncwarp();
    }
}

// ---------------- layer-2 aggregation -> output ----------------
__global__ __launch_bounds__(256) void k_agg2(const float* __restrict__ b2,
                                              float* __restrict__ out) {
    int w = (blockIdx.x * 256 + threadIdx.x) >> 5;
    if (w >= N_NODES) return;
    int lane = threadIdx.x & 31;
    int beg = g_off[w], end = g_off[w + 1];
    float ern = g_er2[w];

    float acc = 0.f, d = 0.f;
    for (int base = beg; base < end; base += 32) {
        int n = min(32, end - base);
        int   s_l = 0;
        float w_l = 0.f;
        if (lane < n) {
            s_l = g_psrc[base + lane];
            w_l = __expf(lrelu(g_el2[s_l] + ern));
        }
        d += w_l;

        int j = 0;
        for (; j + 4 <= n; j += 4) {
            int   ss[4];
            float ws[4], vs[4];
            #pragma unroll
            for (int u = 0; u < 4; u++) {
                ss[u] = __shfl_sync(FULLM, s_l, j + u);
                ws[u] = __shfl_sync(FULLM, w_l, j + u);
            }
            #pragma unroll
            for (int u = 0; u < 4; u++)
                vs[u] = __half2float(g_z2h[(size_t)ss[u] * C_OUT + lane]);
            #pragma unroll
            for (int u = 0; u < 4; u++)
                acc += vs[u] * ws[u];
        }
        for (; j < n; j++) {
            int   s  = __shfl_sync(FULLM, s_l, j);
            float ww = __shfl_sync(FULLM, w_l, j);
            acc += __half2float(g_z2h[(size_t)s * C_OUT + lane]) * ww;
        }
    }

    d = warp_sum(d);
    float inv = d > 0.f ? 1.f / d : 0.f;
    out[(size_t)w * C_OUT + lane] = acc * inv + b2[lane];
}

// ---------------- launch ----------------
extern "C" void kernel_launch(void* const* d_in, const int* in_sizes, int n_in,
                              void* d_out, int out_size) {
    const float* features = (const float*)d_in[0];
    const float* W1  = (const float*)d_in[1];
    const float* al1 = (const float*)d_in[2];
    const float* ar1 = (const float*)d_in[3];
    const float* b1  = (const float*)d_in[4];
    const float* W2  = (const float*)d_in[5];
    const float* al2 = (const float*)d_in[6];
    const float* ar2 = (const float*)d_in[7];
    const float* b2  = (const float*)d_in[8];
    const int*   src = (const int*)d_in[9];
    const int*   dst = (const int*)d_in[10];
    float* out = (float*)d_out;

    // streams/events/symbol addrs created once, reused (host-side only)
    static cudaStream_t s2 = nullptr;
    static cudaEvent_t ev_fork = nullptr, ev_csr = nullptr;
    static void *cnt_ptr = nullptr, *el1_ptr = nullptr, *er1_ptr = nullptr;
    if (!s2) {
        cudaStreamCreateWithFlags(&s2, cudaStreamNonBlocking);
        cudaEventCreateWithFlags(&ev_fork, cudaEventDisableTiming);
        cudaEventCreateWithFlags(&ev_csr, cudaEventDisableTiming);
        cudaGetSymbolAddress(&cnt_ptr, g_cnt);
        cudaGetSymbolAddress(&el1_ptr, g_el1);
        cudaGetSymbolAddress(&er1_ptr, g_er1);
        cudaFuncSetAttribute(k_gemm1_tc, cudaFuncAttributeMaxDynamicSharedMemorySize, G1_SMEM);
    }

    cudaEventRecord(ev_fork, 0);
    cudaStreamWaitEvent(s2, ev_fork, 0);

    // CSR chain on s2: memset + histscan(1) + scatter(2)
    cudaMemsetAsync(cnt_ptr, 0, N_NODES * sizeof(int), s2);
    k_histscan<<<HS_BLOCKS, 1024, 0, s2>>>(dst);
    k_scatter<<<N_EDGES / 256, 256, 0, s2>>>(src, dst);
    cudaEventRecord(ev_csr, s2);

    // main: zero attention accumulators, then GEMM1(+attn epilogue)   [kernel 3]
    cudaMemsetAsync(el1_ptr, 0, N_NODES * NH1 * sizeof(float), 0);
    cudaMemsetAsync(er1_ptr, 0, N_NODES * NH1 * sizeof(float), 0);
    dim3 g1((N_NODES + G1_BM - 1) / G1_BM, (F1T + G1_BN - 1) / G1_BN);
    k_gemm1_tc<<<g1, 256, G1_SMEM>>>(features, W1, al1, ar1);

    // join: fused agg needs CSR + el/er + z1                           [kernel 4]
    cudaStreamWaitEvent(0, ev_csr, 0);
    k_agg1_g2<<<AG_BLOCKS, 256>>>(b1, W2, al2, ar2);

    // layer-2 aggregation                                              [kernel 5]
    k_agg2<<<N_NODES / 8, 256>>>(b2, out);
}

// round 11
// speedup vs baseline: 1.9338x; 1.1452x over previous
#include <cuda_runtime.h>
#include <cuda_fp16.h>
#include <math.h>

#define N_NODES 50000
#define N_EDGES 1600000
#define F_IN    256
#define F1T     200   // H1*F1
#define NH1     2
#define C_OUT   32
#define NEG_SLOPE 0.2f
#define FULLM   0xffffffffu

// ---------------- scratch (static device globals; no allocation) ----------------
__device__ int    g_cnt[N_NODES];
__device__ int    g_off[N_NODES + 1];
__device__ int    g_cur[N_NODES];
__device__ int    g_done;                        // last-block flag for histscan
__device__ int    g_psrc[N_EDGES];               // src node per edge, grouped by dst
__device__ __half g_z1h[(size_t)N_NODES * F1T];  // 20 MB (fp16 z1)
__device__ float  g_el1[N_NODES * NH1];
__device__ float  g_er1[N_NODES * NH1];
__device__ __half g_z2h[(size_t)N_NODES * C_OUT]; // 3.2 MB (fp16 z2)
__device__ float  g_el2[N_NODES];
__device__ float  g_er2[N_NODES];

// ---------------- helpers ----------------
__device__ __forceinline__ float warp_sum(float v) {
    #pragma unroll
    for (int o = 16; o; o >>= 1) v += __shfl_xor_sync(FULLM, v, o);
    return v;
}
__device__ __forceinline__ float lrelu(float x) { return x > 0.f ? x : NEG_SLOPE * x; }
__device__ __forceinline__ float elu1(float x)  { return x > 0.f ? x : (__expf(x) - 1.f); }
__device__ __forceinline__ unsigned tf32u(float x) {
    unsigned u;
    asm("cvt.rna.tf32.f32 %0, %1;" : "=r"(u) : "f"(x));
    return u;
}
// load 4 consecutive halfs -> float4 (8B aligned)
__device__ __forceinline__ float4 ld_half4(const __half* p) {
    uint2 raw = *(const uint2*)p;
    __half2 h0 = *reinterpret_cast<__half2*>(&raw.x);
    __half2 h1 = *reinterpret_cast<__half2*>(&raw.y);
    float2 f0 = __half22float2(h0), f1 = __half22float2(h1);
    return make_float4(f0.x, f0.y, f1.x, f1.y);
}

__device__ __forceinline__ unsigned smem_u32(const void* p) {
    return (unsigned)__cvta_generic_to_shared(p);
}
__device__ __forceinline__ void cp_async16(void* dst_smem, const void* src_gmem) {
    asm volatile("cp.async.cg.shared.global [%0], [%1], 16;\n"
                 :: "r"(smem_u32(dst_smem)), "l"(src_gmem));
}
__device__ __forceinline__ void cp_commit() { asm volatile("cp.async.commit_group;\n"); }
template <int N>
__device__ __forceinline__ void cp_wait() { asm volatile("cp.async.wait_group %0;\n" :: "n"(N)); }

// ---------------- CSR build: fused hist + scan (last-block pattern) ----------------
#define HS_BLOCKS ((N_EDGES + 1023) / 1024)   // 1563
__global__ __launch_bounds__(1024) void k_histscan(const int* __restrict__ dst) {
    int tid = threadIdx.x;
    int e = blockIdx.x * 1024 + tid;
    if (e < N_EDGES) atomicAdd(&g_cnt[dst[e]], 1);

    // last finishing block runs the scan
    __threadfence();
    __shared__ int s_last;
    __syncthreads();
    if (tid == 0) s_last = (atomicAdd(&g_done, 1) == gridDim.x - 1);
    __syncthreads();
    if (!s_last) return;

    const int CH = (N_NODES + 1023) / 1024;  // 49
    int beg = tid * CH;
    int end = min(beg + CH, N_NODES);
    int s = 0;
    for (int i = beg; i < end; i++) s += g_cnt[i];

    __shared__ int warp_sums[32];
    int lane = tid & 31, wid = tid >> 5;
    int v = s;
    #pragma unroll
    for (int o = 1; o < 32; o <<= 1) {
        int t = __shfl_up_sync(FULLM, v, o);
        if (lane >= o) v += t;
    }
    if (lane == 31) warp_sums[wid] = v;
    __syncthreads();
    if (wid == 0) {
        int w = warp_sums[lane];
        #pragma unroll
        for (int o = 1; o < 32; o <<= 1) {
            int t = __shfl_up_sync(FULLM, w, o);
            if (lane >= o) w += t;
        }
        warp_sums[lane] = w;
    }
    __syncthreads();
    int excl = (v - s) + (wid > 0 ? warp_sums[wid - 1] : 0);
    int run = excl;
    for (int i = beg; i < end; i++) {
        int c = g_cnt[i];
        g_off[i] = run;
        g_cur[i] = run;
        run += c;
    }
    if (tid == 1023) g_off[N_NODES] = run;
    if (tid == 0) g_done = 0;   // reset for next replay
}

__global__ void k_scatter(const int* __restrict__ src, const int* __restrict__ dst) {
    int e = blockIdx.x * blockDim.x + threadIdx.x;
    if (e < N_EDGES) {
        int p = atomicAdd(&g_cur[dst[e]], 1);
        g_psrc[p] = src[e];
    }
}

// ---------------- GEMM1 (tf32 mma) -> z1 fp16, + fused attention coefs ----------------
#define G1_BM 128
#define G1_BN 64
#define G1_BK 32
#define G1_LDA 36
#define G1_LDB 72
#define A_STAGE (G1_BM * G1_LDA)
#define B_STAGE (G1_BK * G1_LDB)
#define G1_SMEM ((2 * A_STAGE + 2 * B_STAGE) * 4)   // 55296 bytes dynamic
#define G1_NIT  (F_IN / G1_BK)

__device__ __forceinline__ void mma_tf32(float* d, const unsigned* a, const unsigned* b) {
    asm volatile(
        "mma.sync.aligned.m16n8k8.row.col.f32.tf32.tf32.f32 "
        "{%0,%1,%2,%3}, {%4,%5,%6,%7}, {%8,%9}, {%0,%1,%2,%3};"
        : "+f"(d[0]), "+f"(d[1]), "+f"(d[2]), "+f"(d[3])
        : "r"(a[0]), "r"(a[1]), "r"(a[2]), "r"(a[3]), "r"(b[0]), "r"(b[1]));
}

__global__ __launch_bounds__(256) void k_gemm1_tc(const float* __restrict__ A,
                                                  const float* __restrict__ B,
                                                  const float* __restrict__ al1,
                                                  const float* __restrict__ ar1) {
    extern __shared__ float smem[];
    float* sA = smem;                      // [2][128][36]
    float* sB = smem + 2 * A_STAGE;        // [2][32][72]
    __shared__ float s_al[F1T], s_ar[F1T];

    int tid = threadIdx.x;
    int lane = tid & 31, wid = tid >> 5;
    int wm = wid & 3, wn = wid >> 2;
    int bm = blockIdx.x * G1_BM, bn = blockIdx.y * G1_BN;
    int q = lane >> 2, r = lane & 3;

    for (int i = tid; i < F1T; i += 256) { s_al[i] = al1[i]; s_ar[i] = ar1[i]; }

    int am = tid >> 3;
    int akc = (tid & 7) * 4;

    auto load_stage = [&](int st, int k0) {
        float* a_s = sA + st * A_STAGE;
        float* b_s = sB + st * B_STAGE;
        #pragma unroll
        for (int it = 0; it < 4; it++) {
            int m = am + it * 32;
            float* dstp = &a_s[m * G1_LDA + akc];
            if (bm + m < N_NODES)
                cp_async16(dstp, &A[(size_t)(bm + m) * F_IN + k0 + akc]);
            else
                *(float4*)dstp = make_float4(0.f, 0.f, 0.f, 0.f);
        }
        #pragma unroll
        for (int it = 0; it < 2; it++) {
            int idx = tid + it * 256;
            int kk = idx >> 4;
            int nc = (idx & 15) * 4;
            float* dstp = &b_s[kk * G1_LDB + nc];
            if (bn + nc < F1T)
                cp_async16(dstp, &B[(size_t)(k0 + kk) * F1T + bn + nc]);
            else
                *(float4*)dstp = make_float4(0.f, 0.f, 0.f, 0.f);
        }
        cp_commit();
    };

    float acc[2][4][4] = {};

    load_stage(0, 0);

    #pragma unroll
    for (int it = 0; it < G1_NIT; it++) {
        if (it + 1 < G1_NIT) {
            load_stage((it + 1) & 1, (it + 1) * G1_BK);
            cp_wait<1>();
        } else {
            cp_wait<0>();
        }
        __syncthreads();

        const float* a_s = sA + (it & 1) * A_STAGE;
        const float* b_s = sB + (it & 1) * B_STAGE;

        #pragma unroll
        for (int k8 = 0; k8 < G1_BK / 8; k8++) {
            int kb = k8 * 8;
            unsigned af[2][4], bf[4][2];
            #pragma unroll
            for (int mt = 0; mt < 2; mt++) {
                int m0 = wm * 32 + mt * 16 + q;
                af[mt][0] = tf32u(a_s[m0 * G1_LDA + kb + r]);
                af[mt][1] = tf32u(a_s[(m0 + 8) * G1_LDA + kb + r]);
                af[mt][2] = tf32u(a_s[m0 * G1_LDA + kb + r + 4]);
                af[mt][3] = tf32u(a_s[(m0 + 8) * G1_LDA + kb + r + 4]);
            }
            #pragma unroll
            for (int nt = 0; nt < 4; nt++) {
                int n0 = wn * 32 + nt * 8 + q;
                bf[nt][0] = tf32u(b_s[(kb + r) * G1_LDB + n0]);
                bf[nt][1] = tf32u(b_s[(kb + r + 4) * G1_LDB + n0]);
            }
            #pragma unroll
            for (int mt = 0; mt < 2; mt++)
                #pragma unroll
                for (int nt = 0; nt < 4; nt++)
                    mma_tf32(acc[mt][nt], af[mt], bf[nt]);
        }
        __syncthreads();
    }

    // epilogue A: store z1 as half2
    #pragma unroll
    for (int mt = 0; mt < 2; mt++) {
        #pragma unroll
        for (int nt = 0; nt < 4; nt++) {
            int row = bm + wm * 32 + mt * 16 + q;
            int col = bn + wn * 32 + nt * 8 + 2 * r;
            if (col < F1T) {
                if (row < N_NODES) {
                    __half2 hv = __floats2half2_rn(acc[mt][nt][0], acc[mt][nt][1]);
                    *(__half2*)&g_z1h[(size_t)row * F1T + col] = hv;
                }
                if (row + 8 < N_NODES) {
                    __half2 hv = __floats2half2_rn(acc[mt][nt][2], acc[mt][nt][3]);
                    *(__half2*)&g_z1h[(size_t)(row + 8) * F1T + col] = hv;
                }
            }
        }
    }

    // epilogue B: partial el/er per row (reduce over this thread's 8 cols,
    // then over the 4 lanes sharing q, then atomicAdd)
    #pragma unroll
    for (int mt = 0; mt < 2; mt++) {
        float e0l = 0.f, e1l = 0.f, e0r = 0.f, e1r = 0.f;   // row r0
        float f0l = 0.f, f1l = 0.f, f0r = 0.f, f1r = 0.f;   // row r0+8
        #pragma unroll
        for (int nt = 0; nt < 4; nt++) {
            int colb = bn + wn * 32 + nt * 8 + 2 * r;
            #pragma unroll
            for (int cc = 0; cc < 2; cc++) {
                int c = colb + cc;
                if (c < F1T) {
                    float a = s_al[c], rr = s_ar[c];
                    float zt = acc[mt][nt][cc];
                    float zb = acc[mt][nt][2 + cc];
                    if (c < 100) { e0l += zt * a; e0r += zt * rr; f0l += zb * a; f0r += zb * rr; }
                    else         { e1l += zt * a; e1r += zt * rr; f1l += zb * a; f1r += zb * rr; }
                }
            }
        }
        #pragma unroll
        for (int o = 1; o <= 2; o <<= 1) {
            e0l += __shfl_xor_sync(FULLM, e0l, o); e1l += __shfl_xor_sync(FULLM, e1l, o);
            e0r += __shfl_xor_sync(FULLM, e0r, o); e1r += __shfl_xor_sync(FULLM, e1r, o);
            f0l += __shfl_xor_sync(FULLM, f0l, o); f1l += __shfl_xor_sync(FULLM, f1l, o);
            f0r += __shfl_xor_sync(FULLM, f0r, o); f1r += __shfl_xor_sync(FULLM, f1r, o);
        }
        if (r == 0) {
            int row = bm + wm * 32 + mt * 16 + q;
            if (row < N_NODES) {
                atomicAdd(&g_el1[2 * row],     e0l); atomicAdd(&g_el1[2 * row + 1], e1l);
                atomicAdd(&g_er1[2 * row],     e0r); atomicAdd(&g_er1[2 * row + 1], e1r);
            }
            if (row + 8 < N_NODES) {
                atomicAdd(&g_el1[2 * (row + 8)],     f0l); atomicAdd(&g_el1[2 * (row + 8) + 1], f1l);
                atomicAdd(&g_er1[2 * (row + 8)],     f0r); atomicAdd(&g_er1[2 * (row + 8) + 1], f1r);
            }
        }
    }
}

// ---------------- fused layer-1 aggregation + ELU + GEMM2 + attn2 coefs ----------------
#define AG_BLOCKS (7 * 148)   // 1036: exactly 7 blocks/SM (32KB smem each) in one wave
__global__ __launch_bounds__(256) void k_agg1_g2(const float* __restrict__ b1,
                                                 const float* __restrict__ W2,
                                                 const float* __restrict__ al2,
                                                 const float* __restrict__ ar2) {
    __shared__ float sW[F1T * C_OUT];   // 25.6 KB, W2 row-major [k][c]
    __shared__ float sal[C_OUT], sar[C_OUT];
    __shared__ float sh[8][F1T];        // per-warp h row
    int tid = threadIdx.x;
    for (int i = tid; i < F1T * C_OUT; i += 256) sW[i] = W2[i];
    if (tid < C_OUT) { sal[tid] = al2[tid]; sar[tid] = ar2[tid]; }
    __syncthreads();

    int lane = tid & 31, wid = tid >> 5;
    bool has2 = lane < 18;
    float selA = (lane < 25) ? 1.f : 0.f;   // head boundary at f=100 (4*25)

    for (int w = blockIdx.x * 8 + wid; w < N_NODES; w += AG_BLOCKS * 8) {
        int beg = g_off[w], end = g_off[w + 1];
        float er0 = g_er1[2 * w], er1v = g_er1[2 * w + 1];

        float4 acc0 = make_float4(0.f, 0.f, 0.f, 0.f);
        float4 acc1 = make_float4(0.f, 0.f, 0.f, 0.f);
        float d0 = 0.f, d1 = 0.f;

        for (int base = beg; base < end; base += 32) {
            int n = min(32, end - base);
            int   s_l = 0;
            float w0_l = 0.f, w1_l = 0.f;
            if (lane < n) {
                s_l = g_psrc[base + lane];
                float2 el = *(const float2*)&g_el1[2 * s_l];
                w0_l = __expf(lrelu(el.x + er0));
                w1_l = __expf(lrelu(el.y + er1v));
            }
            d0 += w0_l; d1 += w1_l;

            int j = 0;
            for (; j + 4 <= n; j += 4) {
                int   ss[4];
                float w0s[4], w1s[4];
                #pragma unroll
                for (int u = 0; u < 4; u++) {
                    ss[u]  = __shfl_sync(FULLM, s_l, j + u);
                    w0s[u] = __shfl_sync(FULLM, w0_l, j + u);
                    w1s[u] = __shfl_sync(FULLM, w1_l, j + u);
                }
                float4 v[4], v2[4];
                #pragma unroll
                for (int u = 0; u < 4; u++) {
                    const __half* zr = g_z1h + (size_t)ss[u] * F1T;
                    v[u] = ld_half4(zr + 4 * lane);
                    if (has2) v2[u] = ld_half4(zr + 128 + 4 * lane);
                }
                #pragma unroll
                for (int u = 0; u < 4; u++) {
                    float ww = selA * w0s[u] + (1.f - selA) * w1s[u];
                    acc0.x += v[u].x * ww; acc0.y += v[u].y * ww;
                    acc0.z += v[u].z * ww; acc0.w += v[u].w * ww;
                    if (has2) {
                        acc1.x += v2[u].x * w1s[u]; acc1.y += v2[u].y * w1s[u];
                        acc1.z += v2[u].z * w1s[u]; acc1.w += v2[u].w * w1s[u];
                    }
                }
            }
            for (; j < n; j++) {
                int   s  = __shfl_sync(FULLM, s_l, j);
                float w0 = __shfl_sync(FULLM, w0_l, j);
                float w1 = __shfl_sync(FULLM, w1_l, j);
                const __half* zr = g_z1h + (size_t)s * F1T;
                float4 v = ld_half4(zr + 4 * lane);
                float ww = selA * w0 + (1.f - selA) * w1;
                acc0.x += v.x * ww; acc0.y += v.y * ww;
                acc0.z += v.z * ww; acc0.w += v.w * ww;
                if (has2) {
                    float4 v2 = ld_half4(zr + 128 + 4 * lane);
                    acc1.x += v2.x * w1; acc1.y += v2.y * w1;
                    acc1.z += v2.z * w1; acc1.w += v2.w * w1;
                }
            }
        }

        d0 = warp_sum(d0); d1 = warp_sum(d1);
        float inv0 = d0 > 0.f ? 1.f / d0 : 0.f;
        float inv1 = d1 > 0.f ? 1.f / d1 : 0.f;
        float invA = selA * inv0 + (1.f - selA) * inv1;

        // h = elu(acc/denom + b1) -> smem (never touches gmem)
        float4 bb = *(const float4*)&b1[4 * lane];
        float4 o;
        o.x = elu1(acc0.x * invA + bb.x); o.y = elu1(acc0.y * invA + bb.y);
        o.z = elu1(acc0.z * invA + bb.z); o.w = elu1(acc0.w * invA + bb.w);
        *(float4*)&sh[wid][4 * lane] = o;
        if (has2) {
            float4 bb2 = *(const float4*)&b1[128 + 4 * lane];
            float4 o2;
            o2.x = elu1(acc1.x * inv1 + bb2.x); o2.y = elu1(acc1.y * inv1 + bb2.y);
            o2.z = elu1(acc1.z * inv1 + bb2.z); o2.w = elu1(acc1.w * inv1 + bb2.w);
            *(float4*)&sh[wid][128 + 4 * lane] = o2;
        }
        __syncwarp();

        // z2[c] = h . W2[:,c]  (lane = c)
        float acc2 = 0.f;
        #pragma unroll 5
        for (int k = 0; k < F1T; k += 4) {
            float4 hv = *(const float4*)&sh[wid][k];
            acc2 += hv.x * sW[(k + 0) * C_OUT + lane];
            acc2 += hv.y * sW[(k + 1) * C_OUT + lane];
            acc2 += hv.z * sW[(k + 2) * C_OUT + lane];
            acc2 += hv.w * sW[(k + 3) * C_OUT + lane];
        }
        g_z2h[(size_t)w * C_OUT + lane] = __float2half(acc2);
        float el = warp_sum(acc2 * sal[lane]);
        float er = warp_sum(acc2 * sar[lane]);
        if (lane == 0) { g_el2[w] = el; g_er2[w] = er; }
        __syncwarp();
    }
}

// ---------------- layer-2 aggregation -> output (2 edges per warp-instruction) ----------------
__global__ __launch_bounds__(256) void k_agg2(const float* __restrict__ b2,
                                              float* __restrict__ out) {
    int w = (blockIdx.x * 256 + threadIdx.x) >> 5;
    if (w >= N_NODES) return;
    int lane = threadIdx.x & 31;
    int hw = lane >> 4;            // half-warp id (edge selector)
    int li = lane & 15;            // lane within half-warp -> covers cols 2li, 2li+1
    int beg = g_off[w], end = g_off[w + 1];
    float ern = g_er2[w];

    float2 acc = make_float2(0.f, 0.f);
    float d = 0.f;
    for (int base = beg; base < end; base += 32) {
        int n = min(32, end - base);
        int   s_l = 0;
        float w_l = 0.f;
        if (lane < n) {
            s_l = g_psrc[base + lane];
            w_l = __expf(lrelu(g_el2[s_l] + ern));
        }
        d += w_l;

        // lanes >= n hold s=0, w=0 -> out-of-range edges self-nullify after shfl
        int j = 0;
        for (; j + 4 <= n; j += 4) {
            int   sa = __shfl_sync(FULLM, s_l, j + hw);
            float wa = __shfl_sync(FULLM, w_l, j + hw);
            int   sb = __shfl_sync(FULLM, s_l, j + 2 + hw);
            float wb = __shfl_sync(FULLM, w_l, j + 2 + hw);
            __half2 ha = *(const __half2*)&g_z2h[(size_t)sa * C_OUT + 2 * li];
            __half2 hb = *(const __half2*)&g_z2h[(size_t)sb * C_OUT + 2 * li];
            float2 va = __half22float2(ha);
            float2 vb = __half22float2(hb);
            acc.x += va.x * wa + vb.x * wb;
            acc.y += va.y * wa + vb.y * wb;
        }
        for (; j < n; j += 2) {
            int   sa = __shfl_sync(FULLM, s_l, (j + hw) & 31);
            float wa = __shfl_sync(FULLM, w_l, (j + hw) & 31);
            __half2 ha = *(const __half2*)&g_z2h[(size_t)sa * C_OUT + 2 * li];
            float2 va = __half22float2(ha);
            acc.x += va.x * wa;
            acc.y += va.y * wa;
        }
    }

    // combine the two half-warps (both halves then hold the col-pair sums)
    acc.x += __shfl_xor_sync(FULLM, acc.x, 16);
    acc.y += __shfl_xor_sync(FULLM, acc.y, 16);

    d = warp_sum(d);
    float inv = d > 0.f ? 1.f / d : 0.f;

    if (hw == 0) {
        float2 bb = *(const float2*)&b2[2 * li];
        float2 o = make_float2(acc.x * inv + bb.x, acc.y * inv + bb.y);
        *(float2*)&out[(size_t)w * C_OUT + 2 * li] = o;
    }
}

// ---------------- launch ----------------
extern "C" void kernel_launch(void* const* d_in, const int* in_sizes, int n_in,
                              void* d_out, int out_size) {
    const float* features = (const float*)d_in[0];
    const float* W1  = (const float*)d_in[1];
    const float* al1 = (const float*)d_in[2];
    const float* ar1 = (const float*)d_in[3];
    const float* b1  = (const float*)d_in[4];
    const float* W2  = (const float*)d_in[5];
    const float* al2 = (const float*)d_in[6];
    const float* ar2 = (const float*)d_in[7];
    const float* b2  = (const float*)d_in[8];
    const int*   src = (const int*)d_in[9];
    const int*   dst = (const int*)d_in[10];
    float* out = (float*)d_out;

    // streams/events/symbol addrs created once, reused (host-side only)
    static cudaStream_t s2 = nullptr;
    static cudaEvent_t ev_fork = nullptr, ev_csr = nullptr;
    static void *cnt_ptr = nullptr, *el1_ptr = nullptr, *er1_ptr = nullptr;
    if (!s2) {
        cudaStreamCreateWithFlags(&s2, cudaStreamNonBlocking);
        cudaEventCreateWithFlags(&ev_fork, cudaEventDisableTiming);
        cudaEventCreateWithFlags(&ev_csr, cudaEventDisableTiming);
        cudaGetSymbolAddress(&cnt_ptr, g_cnt);
        cudaGetSymbolAddress(&el1_ptr, g_el1);
        cudaGetSymbolAddress(&er1_ptr, g_er1);
        cudaFuncSetAttribute(k_gemm1_tc, cudaFuncAttributeMaxDynamicSharedMemorySize, G1_SMEM);
    }

    cudaEventRecord(ev_fork, 0);
    cudaStreamWaitEvent(s2, ev_fork, 0);

    // CSR chain on s2: memset + histscan(1) + scatter(2)
    cudaMemsetAsync(cnt_ptr, 0, N_NODES * sizeof(int), s2);
    k_histscan<<<HS_BLOCKS, 1024, 0, s2>>>(dst);
    k_scatter<<<N_EDGES / 256, 256, 0, s2>>>(src, dst);
    cudaEventRecord(ev_csr, s2);

    // main: zero attention accumulators, then GEMM1(+attn epilogue)   [kernel 3]
    cudaMemsetAsync(el1_ptr, 0, N_NODES * NH1 * sizeof(float), 0);
    cudaMemsetAsync(er1_ptr, 0, N_NODES * NH1 * sizeof(float), 0);
    dim3 g1((N_NODES + G1_BM - 1) / G1_BM, (F1T + G1_BN - 1) / G1_BN);
    k_gemm1_tc<<<g1, 256, G1_SMEM>>>(features, W1, al1, ar1);

    // join: fused agg needs CSR + el/er + z1                           [kernel 4]
    cudaStreamWaitEvent(0, ev_csr, 0);
    k_agg1_g2<<<AG_BLOCKS, 256>>>(b1, W2, al2, ar2);

    // layer-2 aggregation                                              [kernel 5]
    k_agg2<<<N_NODES / 8, 256>>>(b2, out);
}

// round 12
// speedup vs baseline: 1.9736x; 1.0206x over previous
#include <cuda_runtime.h>
#include <cuda_fp16.h>
#include <math.h>

#define N_NODES 50000
#define N_EDGES 1600000
#define F_IN    256
#define F1T     200   // H1*F1
#define NH1     2
#define C_OUT   32
#define NEG_SLOPE 0.2f
#define FULLM   0xffffffffu

// ---------------- scratch (static device globals; no allocation) ----------------
__device__ int    g_cnt[N_NODES];
__device__ int    g_off[N_NODES + 1];
__device__ int    g_cur[N_NODES];
__device__ int    g_done;                        // last-block flag for histscan
__device__ int    g_psrc[N_EDGES];               // src node per edge, grouped by dst
__device__ __half g_z1h[(size_t)N_NODES * F1T];  // 20 MB (fp16 z1)
__device__ float  g_el1[N_NODES * NH1];
__device__ float  g_er1[N_NODES * NH1];
__device__ __half g_z2h[(size_t)N_NODES * C_OUT]; // 3.2 MB (fp16 z2)
__device__ float  g_el2[N_NODES];
__device__ float  g_er2[N_NODES];

// ---------------- helpers ----------------
__device__ __forceinline__ float warp_sum(float v) {
    #pragma unroll
    for (int o = 16; o; o >>= 1) v += __shfl_xor_sync(FULLM, v, o);
    return v;
}
__device__ __forceinline__ float lrelu(float x) { return x > 0.f ? x : NEG_SLOPE * x; }
__device__ __forceinline__ float elu1(float x)  { return x > 0.f ? x : (__expf(x) - 1.f); }
__device__ __forceinline__ unsigned tf32u(float x) {
    unsigned u;
    asm("cvt.rna.tf32.f32 %0, %1;" : "=r"(u) : "f"(x));
    return u;
}
// load 4 consecutive halfs -> float4 (8B aligned)
__device__ __forceinline__ float4 ld_half4(const __half* p) {
    uint2 raw = *(const uint2*)p;
    __half2 h0 = *reinterpret_cast<__half2*>(&raw.x);
    __half2 h1 = *reinterpret_cast<__half2*>(&raw.y);
    float2 f0 = __half22float2(h0), f1 = __half22float2(h1);
    return make_float4(f0.x, f0.y, f1.x, f1.y);
}

__device__ __forceinline__ unsigned smem_u32(const void* p) {
    return (unsigned)__cvta_generic_to_shared(p);
}
__device__ __forceinline__ void cp_async16(void* dst_smem, const void* src_gmem) {
    asm volatile("cp.async.cg.shared.global [%0], [%1], 16;\n"
                 :: "r"(smem_u32(dst_smem)), "l"(src_gmem));
}
__device__ __forceinline__ void cp_commit() { asm volatile("cp.async.commit_group;\n"); }
template <int N>
__device__ __forceinline__ void cp_wait() { asm volatile("cp.async.wait_group %0;\n" :: "n"(N)); }

// ---------------- CSR build: fused hist + scan (last-block pattern) ----------------
#define HS_BLOCKS ((N_EDGES + 1023) / 1024)   // 1563
__global__ __launch_bounds__(1024) void k_histscan(const int* __restrict__ dst) {
    int tid = threadIdx.x;
    int e = blockIdx.x * 1024 + tid;
    if (e < N_EDGES) atomicAdd(&g_cnt[dst[e]], 1);

    __threadfence();
    __shared__ int s_last;
    __syncthreads();
    if (tid == 0) s_last = (atomicAdd(&g_done, 1) == gridDim.x - 1);
    __syncthreads();
    if (!s_last) return;

    const int CH = (N_NODES + 1023) / 1024;  // 49
    int beg = tid * CH;
    int end = min(beg + CH, N_NODES);
    int s = 0;
    for (int i = beg; i < end; i++) s += g_cnt[i];

    __shared__ int warp_sums[32];
    int lane = tid & 31, wid = tid >> 5;
    int v = s;
    #pragma unroll
    for (int o = 1; o < 32; o <<= 1) {
        int t = __shfl_up_sync(FULLM, v, o);
        if (lane >= o) v += t;
    }
    if (lane == 31) warp_sums[wid] = v;
    __syncthreads();
    if (wid == 0) {
        int w = warp_sums[lane];
        #pragma unroll
        for (int o = 1; o < 32; o <<= 1) {
            int t = __shfl_up_sync(FULLM, w, o);
            if (lane >= o) w += t;
        }
        warp_sums[lane] = w;
    }
    __syncthreads();
    int excl = (v - s) + (wid > 0 ? warp_sums[wid - 1] : 0);
    int run = excl;
    for (int i = beg; i < end; i++) {
        int c = g_cnt[i];
        g_off[i] = run;
        g_cur[i] = run;
        run += c;
    }
    if (tid == 1023) g_off[N_NODES] = run;
    if (tid == 0) g_done = 0;   // reset for next replay
}

__global__ void k_scatter(const int* __restrict__ src, const int* __restrict__ dst) {
    int e = blockIdx.x * blockDim.x + threadIdx.x;
    if (e < N_EDGES) {
        int p = atomicAdd(&g_cur[dst[e]], 1);
        g_psrc[p] = src[e];
    }
}

// ---------------- GEMM1 (tf32 mma) -> z1 fp16, + fused attention coefs ----------------
#define G1_BM 128
#define G1_BN 64
#define G1_BK 32
#define G1_LDA 36
#define G1_LDB 72
#define A_STAGE (G1_BM * G1_LDA)
#define B_STAGE (G1_BK * G1_LDB)
#define G1_SMEM ((2 * A_STAGE + 2 * B_STAGE) * 4)   // 55296 bytes dynamic
#define G1_NIT  (F_IN / G1_BK)

__device__ __forceinline__ void mma_tf32(float* d, const unsigned* a, const unsigned* b) {
    asm volatile(
        "mma.sync.aligned.m16n8k8.row.col.f32.tf32.tf32.f32 "
        "{%0,%1,%2,%3}, {%4,%5,%6,%7}, {%8,%9}, {%0,%1,%2,%3};"
        : "+f"(d[0]), "+f"(d[1]), "+f"(d[2]), "+f"(d[3])
        : "r"(a[0]), "r"(a[1]), "r"(a[2]), "r"(a[3]), "r"(b[0]), "r"(b[1]));
}

__global__ __launch_bounds__(256) void k_gemm1_tc(const float* __restrict__ A,
                                                  const float* __restrict__ B,
                                                  const float* __restrict__ al1,
                                                  const float* __restrict__ ar1) {
    extern __shared__ float smem[];
    float* sA = smem;                      // [2][128][36]
    float* sB = smem + 2 * A_STAGE;        // [2][32][72]
    __shared__ float s_al[F1T], s_ar[F1T];

    int tid = threadIdx.x;
    int lane = tid & 31, wid = tid >> 5;
    int wm = wid & 3, wn = wid >> 2;
    int bm = blockIdx.x * G1_BM, bn = blockIdx.y * G1_BN;
    int q = lane >> 2, r = lane & 3;

    for (int i = tid; i < F1T; i += 256) { s_al[i] = al1[i]; s_ar[i] = ar1[i]; }

    int am = tid >> 3;
    int akc = (tid & 7) * 4;

    auto load_stage = [&](int st, int k0) {
        float* a_s = sA + st * A_STAGE;
        float* b_s = sB + st * B_STAGE;
        #pragma unroll
        for (int it = 0; it < 4; it++) {
            int m = am + it * 32;
            float* dstp = &a_s[m * G1_LDA + akc];
            if (bm + m < N_NODES)
                cp_async16(dstp, &A[(size_t)(bm + m) * F_IN + k0 + akc]);
            else
                *(float4*)dstp = make_float4(0.f, 0.f, 0.f, 0.f);
        }
        #pragma unroll
        for (int it = 0; it < 2; it++) {
            int idx = tid + it * 256;
            int kk = idx >> 4;
            int nc = (idx & 15) * 4;
            float* dstp = &b_s[kk * G1_LDB + nc];
            if (bn + nc < F1T)
                cp_async16(dstp, &B[(size_t)(k0 + kk) * F1T + bn + nc]);
            else
                *(float4*)dstp = make_float4(0.f, 0.f, 0.f, 0.f);
        }
        cp_commit();
    };

    float acc[2][4][4] = {};

    load_stage(0, 0);

    #pragma unroll
    for (int it = 0; it < G1_NIT; it++) {
        if (it + 1 < G1_NIT) {
            load_stage((it + 1) & 1, (it + 1) * G1_BK);
            cp_wait<1>();
        } else {
            cp_wait<0>();
        }
        __syncthreads();

        const float* a_s = sA + (it & 1) * A_STAGE;
        const float* b_s = sB + (it & 1) * B_STAGE;

        #pragma unroll
        for (int k8 = 0; k8 < G1_BK / 8; k8++) {
            int kb = k8 * 8;
            unsigned af[2][4], bf[4][2];
            #pragma unroll
            for (int mt = 0; mt < 2; mt++) {
                int m0 = wm * 32 + mt * 16 + q;
                af[mt][0] = tf32u(a_s[m0 * G1_LDA + kb + r]);
                af[mt][1] = tf32u(a_s[(m0 + 8) * G1_LDA + kb + r]);
                af[mt][2] = tf32u(a_s[m0 * G1_LDA + kb + r + 4]);
                af[mt][3] = tf32u(a_s[(m0 + 8) * G1_LDA + kb + r + 4]);
            }
            #pragma unroll
            for (int nt = 0; nt < 4; nt++) {
                int n0 = wn * 32 + nt * 8 + q;
                bf[nt][0] = tf32u(b_s[(kb + r) * G1_LDB + n0]);
                bf[nt][1] = tf32u(b_s[(kb + r + 4) * G1_LDB + n0]);
            }
            #pragma unroll
            for (int mt = 0; mt < 2; mt++)
                #pragma unroll
                for (int nt = 0; nt < 4; nt++)
                    mma_tf32(acc[mt][nt], af[mt], bf[nt]);
        }
        __syncthreads();
    }

    // epilogue A: store z1 as half2
    #pragma unroll
    for (int mt = 0; mt < 2; mt++) {
        #pragma unroll
        for (int nt = 0; nt < 4; nt++) {
            int row = bm + wm * 32 + mt * 16 + q;
            int col = bn + wn * 32 + nt * 8 + 2 * r;
            if (col < F1T) {
                if (row < N_NODES) {
                    __half2 hv = __floats2half2_rn(acc[mt][nt][0], acc[mt][nt][1]);
                    *(__half2*)&g_z1h[(size_t)row * F1T + col] = hv;
                }
                if (row + 8 < N_NODES) {
                    __half2 hv = __floats2half2_rn(acc[mt][nt][2], acc[mt][nt][3]);
                    *(__half2*)&g_z1h[(size_t)(row + 8) * F1T + col] = hv;
                }
            }
        }
    }

    // epilogue B: partial el/er per row
    #pragma unroll
    for (int mt = 0; mt < 2; mt++) {
        float e0l = 0.f, e1l = 0.f, e0r = 0.f, e1r = 0.f;   // row r0
        float f0l = 0.f, f1l = 0.f, f0r = 0.f, f1r = 0.f;   // row r0+8
        #pragma unroll
        for (int nt = 0; nt < 4; nt++) {
            int colb = bn + wn * 32 + nt * 8 + 2 * r;
            #pragma unroll
            for (int cc = 0; cc < 2; cc++) {
                int c = colb + cc;
                if (c < F1T) {
                    float a = s_al[c], rr = s_ar[c];
                    float zt = acc[mt][nt][cc];
                    float zb = acc[mt][nt][2 + cc];
                    if (c < 100) { e0l += zt * a; e0r += zt * rr; f0l += zb * a; f0r += zb * rr; }
                    else         { e1l += zt * a; e1r += zt * rr; f1l += zb * a; f1r += zb * rr; }
                }
            }
        }
        #pragma unroll
        for (int o = 1; o <= 2; o <<= 1) {
            e0l += __shfl_xor_sync(FULLM, e0l, o); e1l += __shfl_xor_sync(FULLM, e1l, o);
            e0r += __shfl_xor_sync(FULLM, e0r, o); e1r += __shfl_xor_sync(FULLM, e1r, o);
            f0l += __shfl_xor_sync(FULLM, f0l, o); f1l += __shfl_xor_sync(FULLM, f1l, o);
            f0r += __shfl_xor_sync(FULLM, f0r, o); f1r += __shfl_xor_sync(FULLM, f1r, o);
        }
        if (r == 0) {
            int row = bm + wm * 32 + mt * 16 + q;
            if (row < N_NODES) {
                atomicAdd(&g_el1[2 * row],     e0l); atomicAdd(&g_el1[2 * row + 1], e1l);
                atomicAdd(&g_er1[2 * row],     e0r); atomicAdd(&g_er1[2 * row + 1], e1r);
            }
            if (row + 8 < N_NODES) {
                atomicAdd(&g_el1[2 * (row + 8)],     f0l); atomicAdd(&g_el1[2 * (row + 8) + 1], f1l);
                atomicAdd(&g_er1[2 * (row + 8)],     f0r); atomicAdd(&g_er1[2 * (row + 8) + 1], f1r);
            }
        }
    }
}

// ---------------- fused layer-1 aggregation + ELU + GEMM2 (paired) + attn2 coefs ----------------
#define AG_BLOCKS (6 * 148)   // 888: one wave at 6 blocks/SM (reg-bounded)
#define WT_LD 216             // padded row (halfs): 216*2B=432B -> conflict-free int4 reads
__global__ __launch_bounds__(256, 6) void k_agg1_g2(const float* __restrict__ b1,
                                                    const float* __restrict__ W2,
                                                    const float* __restrict__ al2,
                                                    const float* __restrict__ ar2) {
    __shared__ __half sWt[C_OUT][WT_LD];   // W2 transposed, fp16: 13.8 KB
    __shared__ float sal[C_OUT], sar[C_OUT];
    __shared__ float sh[8][2][F1T];        // per-warp h rows for node pair: 12.8 KB
    int tid = threadIdx.x;
    for (int i = tid; i < F1T * C_OUT; i += 256) {
        int k = i >> 5, c = i & 31;        // i = k*32 + c
        sWt[c][k] = __float2half(W2[i]);
    }
    if (tid < C_OUT) { sal[tid] = al2[tid]; sar[tid] = ar2[tid]; }
    __syncthreads();

    int lane = tid & 31, wid = tid >> 5;
    bool has2 = lane < 18;
    float selA = (lane < 25) ? 1.f : 0.f;   // head boundary at f=100 (4*25)

    for (int p = blockIdx.x * 8 + wid; p < N_NODES / 2; p += AG_BLOCKS * 8) {
        // ---- gather phase: node pair (2p, 2p+1) ----
        #pragma unroll
        for (int hi = 0; hi < 2; hi++) {
            int w = 2 * p + hi;
            int beg = g_off[w], end = g_off[w + 1];
            float er0 = g_er1[2 * w], er1v = g_er1[2 * w + 1];

            float4 acc0 = make_float4(0.f, 0.f, 0.f, 0.f);
            float4 acc1 = make_float4(0.f, 0.f, 0.f, 0.f);
            float d0 = 0.f, d1 = 0.f;

            for (int base = beg; base < end; base += 32) {
                int n = min(32, end - base);
                int   s_l = 0;
                float w0_l = 0.f, w1_l = 0.f;
                if (lane < n) {
                    s_l = g_psrc[base + lane];
                    float2 el = *(const float2*)&g_el1[2 * s_l];
                    w0_l = __expf(lrelu(el.x + er0));
                    w1_l = __expf(lrelu(el.y + er1v));
                }
                d0 += w0_l; d1 += w1_l;

                int j = 0;
                for (; j + 2 <= n; j += 2) {
                    int   sa = __shfl_sync(FULLM, s_l, j);
                    float w0a = __shfl_sync(FULLM, w0_l, j);
                    float w1a = __shfl_sync(FULLM, w1_l, j);
                    int   sb = __shfl_sync(FULLM, s_l, j + 1);
                    float w0b = __shfl_sync(FULLM, w0_l, j + 1);
                    float w1b = __shfl_sync(FULLM, w1_l, j + 1);
                    const __half* za = g_z1h + (size_t)sa * F1T;
                    const __half* zb = g_z1h + (size_t)sb * F1T;
                    float4 va = ld_half4(za + 4 * lane);
                    float4 vb = ld_half4(zb + 4 * lane);
                    float wa = selA * w0a + (1.f - selA) * w1a;
                    float wb = selA * w0b + (1.f - selA) * w1b;
                    acc0.x += va.x * wa + vb.x * wb;
                    acc0.y += va.y * wa + vb.y * wb;
                    acc0.z += va.z * wa + vb.z * wb;
                    acc0.w += va.w * wa + vb.w * wb;
                    if (has2) {
                        float4 v2a = ld_half4(za + 128 + 4 * lane);
                        float4 v2b = ld_half4(zb + 128 + 4 * lane);
                        acc1.x += v2a.x * w1a + v2b.x * w1b;
                        acc1.y += v2a.y * w1a + v2b.y * w1b;
                        acc1.z += v2a.z * w1a + v2b.z * w1b;
                        acc1.w += v2a.w * w1a + v2b.w * w1b;
                    }
                }
                if (j < n) {
                    int   s  = __shfl_sync(FULLM, s_l, j);
                    float w0 = __shfl_sync(FULLM, w0_l, j);
                    float w1 = __shfl_sync(FULLM, w1_l, j);
                    const __half* zr = g_z1h + (size_t)s * F1T;
                    float4 v = ld_half4(zr + 4 * lane);
                    float ww = selA * w0 + (1.f - selA) * w1;
                    acc0.x += v.x * ww; acc0.y += v.y * ww;
                    acc0.z += v.z * ww; acc0.w += v.w * ww;
                    if (has2) {
                        float4 v2 = ld_half4(zr + 128 + 4 * lane);
                        acc1.x += v2.x * w1; acc1.y += v2.y * w1;
                        acc1.z += v2.z * w1; acc1.w += v2.w * w1;
                    }
                }
            }

            d0 = warp_sum(d0); d1 = warp_sum(d1);
            float inv0 = d0 > 0.f ? 1.f / d0 : 0.f;
            float inv1 = d1 > 0.f ? 1.f / d1 : 0.f;
            float invA = selA * inv0 + (1.f - selA) * inv1;

            float4 bb = *(const float4*)&b1[4 * lane];
            float4 o;
            o.x = elu1(acc0.x * invA + bb.x); o.y = elu1(acc0.y * invA + bb.y);
            o.z = elu1(acc0.z * invA + bb.z); o.w = elu1(acc0.w * invA + bb.w);
            *(float4*)&sh[wid][hi][4 * lane] = o;
            if (has2) {
                float4 bb2 = *(const float4*)&b1[128 + 4 * lane];
                float4 o2;
                o2.x = elu1(acc1.x * inv1 + bb2.x); o2.y = elu1(acc1.y * inv1 + bb2.y);
                o2.z = elu1(acc1.z * inv1 + bb2.z); o2.w = elu1(acc1.w * inv1 + bb2.w);
                *(float4*)&sh[wid][hi][128 + 4 * lane] = o2;
            }
        }
        __syncwarp();

        // ---- paired GEMV: z2 = h . W2 for both nodes; lane = output class ----
        float accA = 0.f, accB = 0.f;
        const __half* wrow = &sWt[lane][0];
        #pragma unroll 5
        for (int k = 0; k < F1T; k += 8) {
            float4 a0 = *(const float4*)&sh[wid][0][k];
            float4 a1 = *(const float4*)&sh[wid][0][k + 4];
            float4 c0 = *(const float4*)&sh[wid][1][k];
            float4 c1 = *(const float4*)&sh[wid][1][k + 4];
            uint4 wr = *(const uint4*)&wrow[k];
            float2 wk0 = __half22float2(*reinterpret_cast<__half2*>(&wr.x));
            float2 wk1 = __half22float2(*reinterpret_cast<__half2*>(&wr.y));
            float2 wk2 = __half22float2(*reinterpret_cast<__half2*>(&wr.z));
            float2 wk3 = __half22float2(*reinterpret_cast<__half2*>(&wr.w));
            accA += a0.x * wk0.x + a0.y * wk0.y + a0.z * wk1.x + a0.w * wk1.y
                  + a1.x * wk2.x + a1.y * wk2.y + a1.z * wk3.x + a1.w * wk3.y;
            accB += c0.x * wk0.x + c0.y * wk0.y + c0.z * wk1.x + c0.w * wk1.y
                  + c1.x * wk2.x + c1.y * wk2.y + c1.z * wk3.x + c1.w * wk3.y;
        }

        int wA = 2 * p, wB = 2 * p + 1;
        g_z2h[(size_t)wA * C_OUT + lane] = __float2half(accA);
        g_z2h[(size_t)wB * C_OUT + lane] = __float2half(accB);
        float elA = warp_sum(accA * sal[lane]);
        float erA = warp_sum(accA * sar[lane]);
        float elB = warp_sum(accB * sal[lane]);
        float erB = warp_sum(accB * sar[lane]);
        if (lane == 0) {
            g_el2[wA] = elA; g_er2[wA] = erA;
            g_el2[wB] = elB; g_er2[wB] = erB;
        }
        __syncwarp();
    }
}

// ---------------- layer-2 aggregation -> output (2 edges per warp-instruction) ----------------
__global__ __launch_bounds__(256) void k_agg2(const float* __restrict__ b2,
                                              float* __restrict__ out) {
    int w = (blockIdx.x * 256 + threadIdx.x) >> 5;
    if (w >= N_NODES) return;
    int lane = threadIdx.x & 31;
    int hw = lane >> 4;            // half-warp id (edge selector)
    int li = lane & 15;            // lane within half-warp -> covers cols 2li, 2li+1
    int beg = g_off[w], end = g_off[w + 1];
    float ern = g_er2[w];

    float2 acc = make_float2(0.f, 0.f);
    float d = 0.f;
    for (int base = beg; base < end; base += 32) {
        int n = min(32, end - base);
        int   s_l = 0;
        float w_l = 0.f;
        if (lane < n) {
            s_l = g_psrc[base + lane];
            w_l = __expf(lrelu(g_el2[s_l] + ern));
        }
        d += w_l;

        int j = 0;
        for (; j + 4 <= n; j += 4) {
            int   sa = __shfl_sync(FULLM, s_l, j + hw);
            float wa = __shfl_sync(FULLM, w_l, j + hw);
            int   sb = __shfl_sync(FULLM, s_l, j + 2 + hw);
            float wb = __shfl_sync(FULLM, w_l, j + 2 + hw);
            __half2 ha = *(const __half2*)&g_z2h[(size_t)sa * C_OUT + 2 * li];
            __half2 hb = *(const __half2*)&g_z2h[(size_t)sb * C_OUT + 2 * li];
            float2 va = __half22float2(ha);
            float2 vb = __half22float2(hb);
            acc.x += va.x * wa + vb.x * wb;
            acc.y += va.y * wa + vb.y * wb;
        }
        for (; j < n; j += 2) {
            int   sa = __shfl_sync(FULLM, s_l, (j + hw) & 31);
            float wa = __shfl_sync(FULLM, w_l, (j + hw) & 31);
            __half2 ha = *(const __half2*)&g_z2h[(size_t)sa * C_OUT + 2 * li];
            float2 va = __half22float2(ha);
            acc.x += va.x * wa;
            acc.y += va.y * wa;
        }
    }

    acc.x += __shfl_xor_sync(FULLM, acc.x, 16);
    acc.y += __shfl_xor_sync(FULLM, acc.y, 16);

    d = warp_sum(d);
    float inv = d > 0.f ? 1.f / d : 0.f;

    if (hw == 0) {
        float2 bb = *(const float2*)&b2[2 * li];
        float2 o = make_float2(acc.x * inv + bb.x, acc.y * inv + bb.y);
        *(float2*)&out[(size_t)w * C_OUT + 2 * li] = o;
    }
}

// ---------------- launch ----------------
extern "C" void kernel_launch(void* const* d_in, const int* in_sizes, int n_in,
                              void* d_out, int out_size) {
    const float* features = (const float*)d_in[0];
    const float* W1  = (const float*)d_in[1];
    const float* al1 = (const float*)d_in[2];
    const float* ar1 = (const float*)d_in[3];
    const float* b1  = (const float*)d_in[4];
    const float* W2  = (const float*)d_in[5];
    const float* al2 = (const float*)d_in[6];
    const float* ar2 = (const float*)d_in[7];
    const float* b2  = (const float*)d_in[8];
    const int*   src = (const int*)d_in[9];
    const int*   dst = (const int*)d_in[10];
    float* out = (float*)d_out;

    // streams/events/symbol addrs created once, reused (host-side only)
    static cudaStream_t s2 = nullptr;
    static cudaEvent_t ev_fork = nullptr, ev_csr = nullptr;
    static void *cnt_ptr = nullptr, *el1_ptr = nullptr, *er1_ptr = nullptr;
    if (!s2) {
        cudaStreamCreateWithFlags(&s2, cudaStreamNonBlocking);
        cudaEventCreateWithFlags(&ev_fork, cudaEventDisableTiming);
        cudaEventCreateWithFlags(&ev_csr, cudaEventDisableTiming);
        cudaGetSymbolAddress(&cnt_ptr, g_cnt);
        cudaGetSymbolAddress(&el1_ptr, g_el1);
        cudaGetSymbolAddress(&er1_ptr, g_er1);
        cudaFuncSetAttribute(k_gemm1_tc, cudaFuncAttributeMaxDynamicSharedMemorySize, G1_SMEM);
    }

    cudaEventRecord(ev_fork, 0);
    cudaStreamWaitEvent(s2, ev_fork, 0);

    // CSR chain on s2: memset + histscan(1) + scatter(2)
    cudaMemsetAsync(cnt_ptr, 0, N_NODES * sizeof(int), s2);
    k_histscan<<<HS_BLOCKS, 1024, 0, s2>>>(dst);
    k_scatter<<<N_EDGES / 256, 256, 0, s2>>>(src, dst);
    cudaEventRecord(ev_csr, s2);

    // main: zero attention accumulators, then GEMM1(+attn epilogue)   [kernel 3]
    cudaMemsetAsync(el1_ptr, 0, N_NODES * NH1 * sizeof(float), 0);
    cudaMemsetAsync(er1_ptr, 0, N_NODES * NH1 * sizeof(float), 0);
    dim3 g1((N_NODES + G1_BM - 1) / G1_BM, (F1T + G1_BN - 1) / G1_BN);
    k_gemm1_tc<<<g1, 256, G1_SMEM>>>(features, W1, al1, ar1);

    // join: fused agg needs CSR + el/er + z1                           [kernel 4]
    cudaStreamWaitEvent(0, ev_csr, 0);
    k_agg1_g2<<<AG_BLOCKS, 256>>>(b1, W2, al2, ar2);

    // layer-2 aggregation                                              [kernel 5]
    k_agg2<<<N_NODES / 8, 256>>>(b2, out);
}

// round 13
// speedup vs baseline: 2.0447x; 1.0361x over previous
#include <cuda_runtime.h>
#include <cuda_fp16.h>
#include <math.h>

#define N_NODES 50000
#define N_EDGES 1600000
#define F_IN    256
#define F1T     200   // H1*F1
#define NH1     2
#define C_OUT   32
#define NEG_SLOPE 0.2f
#define FULLM   0xffffffffu

// ---------------- scratch (static device globals; no allocation) ----------------
__device__ int    g_cnt[N_NODES];
__device__ int    g_off[N_NODES + 1];
__device__ int    g_cur[N_NODES];
__device__ int    g_done;                        // last-block flag for histscan
__device__ int    g_psrc[N_EDGES];               // src node per edge, grouped by dst
__device__ __half g_z1h[(size_t)N_NODES * F1T];  // 20 MB (fp16 z1)
__device__ float  g_el1[N_NODES * NH1];
__device__ float  g_er1[N_NODES * NH1];
__device__ __half g_z2h[(size_t)N_NODES * C_OUT]; // 3.2 MB (fp16 z2)
__device__ float  g_el2[N_NODES];
__device__ float  g_er2[N_NODES];

// ---------------- helpers ----------------
__device__ __forceinline__ float warp_sum(float v) {
    #pragma unroll
    for (int o = 16; o; o >>= 1) v += __shfl_xor_sync(FULLM, v, o);
    return v;
}
__device__ __forceinline__ float lrelu(float x) { return x > 0.f ? x : NEG_SLOPE * x; }
__device__ __forceinline__ float elu1(float x)  { return x > 0.f ? x : (__expf(x) - 1.f); }
__device__ __forceinline__ unsigned tf32u(float x) {
    unsigned u;
    asm("cvt.rna.tf32.f32 %0, %1;" : "=r"(u) : "f"(x));
    return u;
}
// accumulate 8 halfs (uint4) * {wlo (first 4), whi (last 4)} into acc[8]
__device__ __forceinline__ void hfma8(float* acc, uint4 r, float wlo, float whi) {
    float2 p0 = __half22float2(*reinterpret_cast<__half2*>(&r.x));
    float2 p1 = __half22float2(*reinterpret_cast<__half2*>(&r.y));
    float2 p2 = __half22float2(*reinterpret_cast<__half2*>(&r.z));
    float2 p3 = __half22float2(*reinterpret_cast<__half2*>(&r.w));
    acc[0] += p0.x * wlo; acc[1] += p0.y * wlo;
    acc[2] += p1.x * wlo; acc[3] += p1.y * wlo;
    acc[4] += p2.x * whi; acc[5] += p2.y * whi;
    acc[6] += p3.x * whi; acc[7] += p3.y * whi;
}

__device__ __forceinline__ unsigned smem_u32(const void* p) {
    return (unsigned)__cvta_generic_to_shared(p);
}
__device__ __forceinline__ void cp_async16(void* dst_smem, const void* src_gmem) {
    asm volatile("cp.async.cg.shared.global [%0], [%1], 16;\n"
                 :: "r"(smem_u32(dst_smem)), "l"(src_gmem));
}
__device__ __forceinline__ void cp_commit() { asm volatile("cp.async.commit_group;\n"); }
template <int N>
__device__ __forceinline__ void cp_wait() { asm volatile("cp.async.wait_group %0;\n" :: "n"(N)); }

// ---------------- CSR build: fused hist + scan (last-block pattern) ----------------
#define HS_BLOCKS ((N_EDGES + 1023) / 1024)   // 1563
__global__ __launch_bounds__(1024) void k_histscan(const int* __restrict__ dst) {
    int tid = threadIdx.x;
    int e = blockIdx.x * 1024 + tid;
    if (e < N_EDGES) atomicAdd(&g_cnt[dst[e]], 1);

    __threadfence();
    __shared__ int s_last;
    __syncthreads();
    if (tid == 0) s_last = (atomicAdd(&g_done, 1) == gridDim.x - 1);
    __syncthreads();
    if (!s_last) return;

    const int CH = (N_NODES + 1023) / 1024;  // 49
    int beg = tid * CH;
    int end = min(beg + CH, N_NODES);
    int s = 0;
    for (int i = beg; i < end; i++) s += g_cnt[i];

    __shared__ int warp_sums[32];
    int lane = tid & 31, wid = tid >> 5;
    int v = s;
    #pragma unroll
    for (int o = 1; o < 32; o <<= 1) {
        int t = __shfl_up_sync(FULLM, v, o);
        if (lane >= o) v += t;
    }
    if (lane == 31) warp_sums[wid] = v;
    __syncthreads();
    if (wid == 0) {
        int w = warp_sums[lane];
        #pragma unroll
        for (int o = 1; o < 32; o <<= 1) {
            int t = __shfl_up_sync(FULLM, w, o);
            if (lane >= o) w += t;
        }
        warp_sums[lane] = w;
    }
    __syncthreads();
    int excl = (v - s) + (wid > 0 ? warp_sums[wid - 1] : 0);
    int run = excl;
    for (int i = beg; i < end; i++) {
        int c = g_cnt[i];
        g_off[i] = run;
        g_cur[i] = run;
        run += c;
    }
    if (tid == 1023) g_off[N_NODES] = run;
    if (tid == 0) g_done = 0;   // reset for next replay
}

__global__ void k_scatter(const int* __restrict__ src, const int* __restrict__ dst) {
    int e = blockIdx.x * blockDim.x + threadIdx.x;
    if (e < N_EDGES) {
        int p = atomicAdd(&g_cur[dst[e]], 1);
        g_psrc[p] = src[e];
    }
}

// ---------------- GEMM1 (tf32 mma) -> z1 fp16, + fused attention coefs ----------------
#define G1_BM 128
#define G1_BN 64
#define G1_BK 32
#define G1_LDA 36
#define G1_LDB 72
#define A_STAGE (G1_BM * G1_LDA)
#define B_STAGE (G1_BK * G1_LDB)
#define G1_SMEM ((2 * A_STAGE + 2 * B_STAGE) * 4)   // 55296 bytes dynamic
#define G1_NIT  (F_IN / G1_BK)

__device__ __forceinline__ void mma_tf32(float* d, const unsigned* a, const unsigned* b) {
    asm volatile(
        "mma.sync.aligned.m16n8k8.row.col.f32.tf32.tf32.f32 "
        "{%0,%1,%2,%3}, {%4,%5,%6,%7}, {%8,%9}, {%0,%1,%2,%3};"
        : "+f"(d[0]), "+f"(d[1]), "+f"(d[2]), "+f"(d[3])
        : "r"(a[0]), "r"(a[1]), "r"(a[2]), "r"(a[3]), "r"(b[0]), "r"(b[1]));
}

__global__ __launch_bounds__(256) void k_gemm1_tc(const float* __restrict__ A,
                                                  const float* __restrict__ B,
                                                  const float* __restrict__ al1,
                                                  const float* __restrict__ ar1) {
    extern __shared__ float smem[];
    float* sA = smem;                      // [2][128][36]
    float* sB = smem + 2 * A_STAGE;        // [2][32][72]
    __shared__ float s_al[F1T], s_ar[F1T];

    int tid = threadIdx.x;
    int lane = tid & 31, wid = tid >> 5;
    int wm = wid & 3, wn = wid >> 2;
    int bm = blockIdx.x * G1_BM, bn = blockIdx.y * G1_BN;
    int q = lane >> 2, r = lane & 3;

    for (int i = tid; i < F1T; i += 256) { s_al[i] = al1[i]; s_ar[i] = ar1[i]; }

    int am = tid >> 3;
    int akc = (tid & 7) * 4;

    auto load_stage = [&](int st, int k0) {
        float* a_s = sA + st * A_STAGE;
        float* b_s = sB + st * B_STAGE;
        #pragma unroll
        for (int it = 0; it < 4; it++) {
            int m = am + it * 32;
            float* dstp = &a_s[m * G1_LDA + akc];
            if (bm + m < N_NODES)
                cp_async16(dstp, &A[(size_t)(bm + m) * F_IN + k0 + akc]);
            else
                *(float4*)dstp = make_float4(0.f, 0.f, 0.f, 0.f);
        }
        #pragma unroll
        for (int it = 0; it < 2; it++) {
            int idx = tid + it * 256;
            int kk = idx >> 4;
            int nc = (idx & 15) * 4;
            float* dstp = &b_s[kk * G1_LDB + nc];
            if (bn + nc < F1T)
                cp_async16(dstp, &B[(size_t)(k0 + kk) * F1T + bn + nc]);
            else
                *(float4*)dstp = make_float4(0.f, 0.f, 0.f, 0.f);
        }
        cp_commit();
    };

    float acc[2][4][4] = {};

    load_stage(0, 0);

    #pragma unroll
    for (int it = 0; it < G1_NIT; it++) {
        if (it + 1 < G1_NIT) {
            load_stage((it + 1) & 1, (it + 1) * G1_BK);
            cp_wait<1>();
        } else {
            cp_wait<0>();
        }
        __syncthreads();

        const float* a_s = sA + (it & 1) * A_STAGE;
        const float* b_s = sB + (it & 1) * B_STAGE;

        #pragma unroll
        for (int k8 = 0; k8 < G1_BK / 8; k8++) {
            int kb = k8 * 8;
            unsigned af[2][4], bf[4][2];
            #pragma unroll
            for (int mt = 0; mt < 2; mt++) {
                int m0 = wm * 32 + mt * 16 + q;
                af[mt][0] = tf32u(a_s[m0 * G1_LDA + kb + r]);
                af[mt][1] = tf32u(a_s[(m0 + 8) * G1_LDA + kb + r]);
                af[mt][2] = tf32u(a_s[m0 * G1_LDA + kb + r + 4]);
                af[mt][3] = tf32u(a_s[(m0 + 8) * G1_LDA + kb + r + 4]);
            }
            #pragma unroll
            for (int nt = 0; nt < 4; nt++) {
                int n0 = wn * 32 + nt * 8 + q;
                bf[nt][0] = tf32u(b_s[(kb + r) * G1_LDB + n0]);
                bf[nt][1] = tf32u(b_s[(kb + r + 4) * G1_LDB + n0]);
            }
            #pragma unroll
            for (int mt = 0; mt < 2; mt++)
                #pragma unroll
                for (int nt = 0; nt < 4; nt++)
                    mma_tf32(acc[mt][nt], af[mt], bf[nt]);
        }
        __syncthreads();
    }

    // epilogue A: store z1 as half2
    #pragma unroll
    for (int mt = 0; mt < 2; mt++) {
        #pragma unroll
        for (int nt = 0; nt < 4; nt++) {
            int row = bm + wm * 32 + mt * 16 + q;
            int col = bn + wn * 32 + nt * 8 + 2 * r;
            if (col < F1T) {
                if (row < N_NODES) {
                    __half2 hv = __floats2half2_rn(acc[mt][nt][0], acc[mt][nt][1]);
                    *(__half2*)&g_z1h[(size_t)row * F1T + col] = hv;
                }
                if (row + 8 < N_NODES) {
                    __half2 hv = __floats2half2_rn(acc[mt][nt][2], acc[mt][nt][3]);
                    *(__half2*)&g_z1h[(size_t)(row + 8) * F1T + col] = hv;
                }
            }
        }
    }

    // epilogue B: partial el/er per row
    #pragma unroll
    for (int mt = 0; mt < 2; mt++) {
        float e0l = 0.f, e1l = 0.f, e0r = 0.f, e1r = 0.f;   // row r0
        float f0l = 0.f, f1l = 0.f, f0r = 0.f, f1r = 0.f;   // row r0+8
        #pragma unroll
        for (int nt = 0; nt < 4; nt++) {
            int colb = bn + wn * 32 + nt * 8 + 2 * r;
            #pragma unroll
            for (int cc = 0; cc < 2; cc++) {
                int c = colb + cc;
                if (c < F1T) {
                    float a = s_al[c], rr = s_ar[c];
                    float zt = acc[mt][nt][cc];
                    float zb = acc[mt][nt][2 + cc];
                    if (c < 100) { e0l += zt * a; e0r += zt * rr; f0l += zb * a; f0r += zb * rr; }
                    else         { e1l += zt * a; e1r += zt * rr; f1l += zb * a; f1r += zb * rr; }
                }
            }
        }
        #pragma unroll
        for (int o = 1; o <= 2; o <<= 1) {
            e0l += __shfl_xor_sync(FULLM, e0l, o); e1l += __shfl_xor_sync(FULLM, e1l, o);
            e0r += __shfl_xor_sync(FULLM, e0r, o); e1r += __shfl_xor_sync(FULLM, e1r, o);
            f0l += __shfl_xor_sync(FULLM, f0l, o); f1l += __shfl_xor_sync(FULLM, f1l, o);
            f0r += __shfl_xor_sync(FULLM, f0r, o); f1r += __shfl_xor_sync(FULLM, f1r, o);
        }
        if (r == 0) {
            int row = bm + wm * 32 + mt * 16 + q;
            if (row < N_NODES) {
                atomicAdd(&g_el1[2 * row],     e0l); atomicAdd(&g_el1[2 * row + 1], e1l);
                atomicAdd(&g_er1[2 * row],     e0r); atomicAdd(&g_er1[2 * row + 1], e1r);
            }
            if (row + 8 < N_NODES) {
                atomicAdd(&g_el1[2 * (row + 8)],     f0l); atomicAdd(&g_el1[2 * (row + 8) + 1], f1l);
                atomicAdd(&g_er1[2 * (row + 8)],     f0r); atomicAdd(&g_er1[2 * (row + 8) + 1], f1r);
            }
        }
    }
}

// ---------------- fused layer-1 aggregation + ELU + GEMM2 (paired) + attn2 coefs ----------------
// Gather layout: lane l (<25) covers features 8l..8l+7 via ONE 16B load per edge.
// Head boundary f=100: inside lane 12 only -> wlo = (l<=12)?w0:w1, whi = (l<=11)?w0:w1.
#define AG_BLOCKS (6 * 148)   // 888: one wave at 6 blocks/SM
#define WT_LD 216             // padded row (halfs): conflict-free int4 reads
__global__ __launch_bounds__(256, 6) void k_agg1_g2(const float* __restrict__ b1,
                                                    const float* __restrict__ W2,
                                                    const float* __restrict__ al2,
                                                    const float* __restrict__ ar2) {
    __shared__ __half sWt[C_OUT][WT_LD];   // W2 transposed, fp16: 13.8 KB
    __shared__ float sal[C_OUT], sar[C_OUT];
    __shared__ float sh[8][2][F1T];        // per-warp h rows for node pair: 12.8 KB
    int tid = threadIdx.x;
    for (int i = tid; i < F1T * C_OUT; i += 256) {
        int k = i >> 5, c = i & 31;        // i = k*32 + c
        sWt[c][k] = __float2half(W2[i]);
    }
    if (tid < C_OUT) { sal[tid] = al2[tid]; sar[tid] = ar2[tid]; }
    __syncthreads();

    int lane = tid & 31, wid = tid >> 5;
    bool active = lane < 25;               // lanes covering features
    bool lo0 = lane <= 12;                 // first 4 feats in head0?
    bool hi0 = lane <= 11;                 // last 4 feats in head0?

    for (int p = blockIdx.x * 8 + wid; p < N_NODES / 2; p += AG_BLOCKS * 8) {
        // ---- gather phase: node pair (2p, 2p+1) ----
        #pragma unroll
        for (int hi = 0; hi < 2; hi++) {
            int w = 2 * p + hi;
            int beg = g_off[w], end = g_off[w + 1];
            float er0 = g_er1[2 * w], er1v = g_er1[2 * w + 1];

            float acc[8] = {};
            float d0 = 0.f, d1 = 0.f;

            for (int base = beg; base < end; base += 32) {
                int n = min(32, end - base);
                int   s_l = 0;
                float w0_l = 0.f, w1_l = 0.f;
                if (lane < n) {
                    s_l = g_psrc[base + lane];
                    float2 el = *(const float2*)&g_el1[2 * s_l];
                    w0_l = __expf(lrelu(el.x + er0));
                    w1_l = __expf(lrelu(el.y + er1v));
                }
                d0 += w0_l; d1 += w1_l;

                int j = 0;
                for (; j + 2 <= n; j += 2) {
                    int   sa  = __shfl_sync(FULLM, s_l, j);
                    float w0a = __shfl_sync(FULLM, w0_l, j);
                    float w1a = __shfl_sync(FULLM, w1_l, j);
                    int   sb  = __shfl_sync(FULLM, s_l, j + 1);
                    float w0b = __shfl_sync(FULLM, w0_l, j + 1);
                    float w1b = __shfl_sync(FULLM, w1_l, j + 1);
                    if (active) {
                        uint4 ra = *(const uint4*)(g_z1h + (size_t)sa * F1T + 8 * lane);
                        uint4 rb = *(const uint4*)(g_z1h + (size_t)sb * F1T + 8 * lane);
                        hfma8(acc, ra, lo0 ? w0a : w1a, hi0 ? w0a : w1a);
                        hfma8(acc, rb, lo0 ? w0b : w1b, hi0 ? w0b : w1b);
                    }
                }
                if (j < n) {
                    int   s  = __shfl_sync(FULLM, s_l, j);
                    float w0 = __shfl_sync(FULLM, w0_l, j);
                    float w1 = __shfl_sync(FULLM, w1_l, j);
                    if (active) {
                        uint4 rr = *(const uint4*)(g_z1h + (size_t)s * F1T + 8 * lane);
                        hfma8(acc, rr, lo0 ? w0 : w1, hi0 ? w0 : w1);
                    }
                }
            }

            d0 = warp_sum(d0); d1 = warp_sum(d1);
            float inv0 = d0 > 0.f ? 1.f / d0 : 0.f;
            float inv1 = d1 > 0.f ? 1.f / d1 : 0.f;
            float inv_lo = lo0 ? inv0 : inv1;
            float inv_hi = hi0 ? inv0 : inv1;

            if (active) {
                float4 blo = *(const float4*)&b1[8 * lane];
                float4 bhi = *(const float4*)&b1[8 * lane + 4];
                float4 o0, o1;
                o0.x = elu1(acc[0] * inv_lo + blo.x);
                o0.y = elu1(acc[1] * inv_lo + blo.y);
                o0.z = elu1(acc[2] * inv_lo + blo.z);
                o0.w = elu1(acc[3] * inv_lo + blo.w);
                o1.x = elu1(acc[4] * inv_hi + bhi.x);
                o1.y = elu1(acc[5] * inv_hi + bhi.y);
                o1.z = elu1(acc[6] * inv_hi + bhi.z);
                o1.w = elu1(acc[7] * inv_hi + bhi.w);
                *(float4*)&sh[wid][hi][8 * lane]     = o0;
                *(float4*)&sh[wid][hi][8 * lane + 4] = o1;
            }
        }
        __syncwarp();

        // ---- paired GEMV: z2 = h . W2 for both nodes; lane = output class ----
        float accA = 0.f, accB = 0.f;
        const __half* wrow = &sWt[lane][0];
        #pragma unroll 5
        for (int k = 0; k < F1T; k += 8) {
            float4 a0 = *(const float4*)&sh[wid][0][k];
            float4 a1 = *(const float4*)&sh[wid][0][k + 4];
            float4 c0 = *(const float4*)&sh[wid][1][k];
            float4 c1 = *(const float4*)&sh[wid][1][k + 4];
            uint4 wr = *(const uint4*)&wrow[k];
            float2 wk0 = __half22float2(*reinterpret_cast<__half2*>(&wr.x));
            float2 wk1 = __half22float2(*reinterpret_cast<__half2*>(&wr.y));
            float2 wk2 = __half22float2(*reinterpret_cast<__half2*>(&wr.z));
            float2 wk3 = __half22float2(*reinterpret_cast<__half2*>(&wr.w));
            accA += a0.x * wk0.x + a0.y * wk0.y + a0.z * wk1.x + a0.w * wk1.y
                  + a1.x * wk2.x + a1.y * wk2.y + a1.z * wk3.x + a1.w * wk3.y;
            accB += c0.x * wk0.x + c0.y * wk0.y + c0.z * wk1.x + c0.w * wk1.y
                  + c1.x * wk2.x + c1.y * wk2.y + c1.z * wk3.x + c1.w * wk3.y;
        }

        int wA = 2 * p, wB = 2 * p + 1;
        g_z2h[(size_t)wA * C_OUT + lane] = __float2half(accA);
        g_z2h[(size_t)wB * C_OUT + lane] = __float2half(accB);
        float elA = warp_sum(accA * sal[lane]);
        float erA = warp_sum(accA * sar[lane]);
        float elB = warp_sum(accB * sal[lane]);
        float erB = warp_sum(accB * sar[lane]);
        if (lane == 0) {
            g_el2[wA] = elA; g_er2[wA] = erA;
            g_el2[wB] = elB; g_er2[wB] = erB;
        }
        __syncwarp();
    }
}

// ---------------- layer-2 aggregation -> output (2 edges per warp-instruction) ----------------
__global__ __launch_bounds__(256) void k_agg2(const float* __restrict__ b2,
                                              float* __restrict__ out) {
    int w = (blockIdx.x * 256 + threadIdx.x) >> 5;
    if (w >= N_NODES) return;
    int lane = threadIdx.x & 31;
    int hw = lane >> 4;            // half-warp id (edge selector)
    int li = lane & 15;            // lane within half-warp -> covers cols 2li, 2li+1
    int beg = g_off[w], end = g_off[w + 1];
    float ern = g_er2[w];

    float2 acc = make_float2(0.f, 0.f);
    float d = 0.f;
    for (int base = beg; base < end; base += 32) {
        int n = min(32, end - base);
        int   s_l = 0;
        float w_l = 0.f;
        if (lane < n) {
            s_l = g_psrc[base + lane];
            w_l = __expf(lrelu(g_el2[s_l] + ern));
        }
        d += w_l;

        int j = 0;
        for (; j + 4 <= n; j += 4) {
            int   sa = __shfl_sync(FULLM, s_l, j + hw);
            float wa = __shfl_sync(FULLM, w_l, j + hw);
            int   sb = __shfl_sync(FULLM, s_l, j + 2 + hw);
            float wb = __shfl_sync(FULLM, w_l, j + 2 + hw);
            __half2 ha = *(const __half2*)&g_z2h[(size_t)sa * C_OUT + 2 * li];
            __half2 hb = *(const __half2*)&g_z2h[(size_t)sb * C_OUT + 2 * li];
            float2 va = __half22float2(ha);
            float2 vb = __half22float2(hb);
            acc.x += va.x * wa + vb.x * wb;
            acc.y += va.y * wa + vb.y * wb;
        }
        for (; j < n; j += 2) {
            int   sa = __shfl_sync(FULLM, s_l, (j + hw) & 31);
            float wa = __shfl_sync(FULLM, w_l, (j + hw) & 31);
            __half2 ha = *(const __half2*)&g_z2h[(size_t)sa * C_OUT + 2 * li];
            float2 va = __half22float2(ha);
            acc.x += va.x * wa;
            acc.y += va.y * wa;
        }
    }

    acc.x += __shfl_xor_sync(FULLM, acc.x, 16);
    acc.y += __shfl_xor_sync(FULLM, acc.y, 16);

    d = warp_sum(d);
    float inv = d > 0.f ? 1.f / d : 0.f;

    if (hw == 0) {
        float2 bb = *(const float2*)&b2[2 * li];
        float2 o = make_float2(acc.x * inv + bb.x, acc.y * inv + bb.y);
        *(float2*)&out[(size_t)w * C_OUT + 2 * li] = o;
    }
}

// ---------------- launch ----------------
extern "C" void kernel_launch(void* const* d_in, const int* in_sizes, int n_in,
                              void* d_out, int out_size) {
    const float* features = (const float*)d_in[0];
    const float* W1  = (const float*)d_in[1];
    const float* al1 = (const float*)d_in[2];
    const float* ar1 = (const float*)d_in[3];
    const float* b1  = (const float*)d_in[4];
    const float* W2  = (const float*)d_in[5];
    const float* al2 = (const float*)d_in[6];
    const float* ar2 = (const float*)d_in[7];
    const float* b2  = (const float*)d_in[8];
    const int*   src = (const int*)d_in[9];
    const int*   dst = (const int*)d_in[10];
    float* out = (float*)d_out;

    // streams/events/symbol addrs created once, reused (host-side only)
    static cudaStream_t s2 = nullptr;
    static cudaEvent_t ev_fork = nullptr, ev_csr = nullptr;
    static void *cnt_ptr = nullptr, *el1_ptr = nullptr, *er1_ptr = nullptr;
    if (!s2) {
        cudaStreamCreateWithFlags(&s2, cudaStreamNonBlocking);
        cudaEventCreateWithFlags(&ev_fork, cudaEventDisableTiming);
        cudaEventCreateWithFlags(&ev_csr, cudaEventDisableTiming);
        cudaGetSymbolAddress(&cnt_ptr, g_cnt);
        cudaGetSymbolAddress(&el1_ptr, g_el1);
        cudaGetSymbolAddress(&er1_ptr, g_er1);
        cudaFuncSetAttribute(k_gemm1_tc, cudaFuncAttributeMaxDynamicSharedMemorySize, G1_SMEM);
    }

    cudaEventRecord(ev_fork, 0);
    cudaStreamWaitEvent(s2, ev_fork, 0);

    // CSR chain on s2: memset + histscan(1) + scatter(2)
    cudaMemsetAsync(cnt_ptr, 0, N_NODES * sizeof(int), s2);
    k_histscan<<<HS_BLOCKS, 1024, 0, s2>>>(dst);
    k_scatter<<<N_EDGES / 256, 256, 0, s2>>>(src, dst);
    cudaEventRecord(ev_csr, s2);

    // main: zero attention accumulators, then GEMM1(+attn epilogue)   [kernel 3]
    cudaMemsetAsync(el1_ptr, 0, N_NODES * NH1 * sizeof(float), 0);
    cudaMemsetAsync(er1_ptr, 0, N_NODES * NH1 * sizeof(float), 0);
    dim3 g1((N_NODES + G1_BM - 1) / G1_BM, (F1T + G1_BN - 1) / G1_BN);
    k_gemm1_tc<<<g1, 256, G1_SMEM>>>(features, W1, al1, ar1);

    // join: fused agg needs CSR + el/er + z1                           [kernel 4]
    cudaStreamWaitEvent(0, ev_csr, 0);
    k_agg1_g2<<<AG_BLOCKS, 256>>>(b1, W2, al2, ar2);

    // layer-2 aggregation                                              [kernel 5]
    k_agg2<<<N_NODES / 8, 256>>>(b2, out);
}